// round 12
// baseline (speedup 1.0000x reference)
#include <cuda_runtime.h>
#include <cuda_fp16.h>
#include <cstdint>

#define BB 4
#define TT 4096
#define CC 1024
#define HH 16
#define DD 64
#define MM (BB*TT)   // 16384

// Scratch (device globals — no allocation allowed)
__device__ __half g_attn[(size_t)MM*CC];
__device__ __half g_xc[(size_t)MM*CC];
__device__ __half g_yc[(size_t)MM*CC];
__device__ __half g_wqc[CC*CC];
__device__ __half g_wkc[CC*CC];
__device__ __half g_wvc[CC*CC];
__device__ __half g_wpc[CC*CC];
__device__ float  g_ksum[BB*CC];
__device__ float  g_kv[BB*HH*DD*DD];

__device__ __forceinline__ uint32_t smem_u32(const void* p) {
    uint32_t a;
    asm("{ .reg .u64 t; cvta.to.shared.u64 t, %1; cvt.u32.u64 %0, t; }" : "=r"(a) : "l"(p));
    return a;
}

#define CP_ASYNC16(saddr, gptr) \
    asm volatile("cp.async.cg.shared.global [%0], [%1], 16;" :: "r"(saddr), "l"(gptr))
#define CP_COMMIT() asm volatile("cp.async.commit_group;" ::: "memory")
#define CP_WAIT1()  asm volatile("cp.async.wait_group 1;" ::: "memory")

__device__ __forceinline__ void mma_f16(float* c, const uint32_t* a, const uint32_t* b) {
    asm volatile(
        "mma.sync.aligned.m16n8k16.row.col.f32.f16.f16.f32 "
        "{%0,%1,%2,%3}, {%4,%5,%6,%7}, {%8,%9}, {%0,%1,%2,%3};"
        : "+f"(c[0]), "+f"(c[1]), "+f"(c[2]), "+f"(c[3])
        : "r"(a[0]), "r"(a[1]), "r"(a[2]), "r"(a[3]), "r"(b[0]), "r"(b[1]));
}

#define LDSM_X4(r0, r1, r2, r3, addr) \
    asm volatile("ldmatrix.sync.aligned.m8n8.x4.shared.b16 {%0,%1,%2,%3}, [%4];" \
                 : "=r"(r0), "=r"(r1), "=r"(r2), "=r"(r3) : "r"(addr))
#define LDSM_X4_T(r0, r1, r2, r3, addr) \
    asm volatile("ldmatrix.sync.aligned.m8n8.x4.trans.shared.b16 {%0,%1,%2,%3}, [%4];" \
                 : "=r"(r0), "=r"(r1), "=r"(r2), "=r"(r3) : "r"(addr))

#define PITCHB 144
#define A_TILE_BYTES (128*PITCHB)      // 18432
#define STAGE_BYTES (2*A_TILE_BYTES)   // 36864   (Q/P kernel)
#define GEMM_SMEM (3*STAGE_BYTES)      // 110592
#define STAGE3_BYTES (3*A_TILE_BYTES)  // 55296   (KV kernel)
#define KV_SMEM (3*STAGE3_BYTES)       // 165888
#define NITER 16
#define KVPITCH 272                    // epilogue tile pitch (136 halfs)

// ============================================================================
// KV mega-kernel (512 threads) — unchanged from R11
// ============================================================================
__global__ __launch_bounds__(512, 1)
void gemm_kv(const __half* __restrict__ A,
             const __half* __restrict__ Wk, const __half* __restrict__ Wv,
             const float* __restrict__ bk, const float* __restrict__ bv,
             float* __restrict__ kv_out, float* __restrict__ ksum_out)
{
    extern __shared__ char smem[];
    const int tid  = threadIdx.x;
    const int wid  = tid >> 5;
    const int lane = tid & 31;
    const int g    = lane >> 2;
    const int tig  = lane & 3;
    const int grp  = wid >> 3;        // 0 = K, 1 = V
    const int kwid = wid & 7;
    const int wm   = kwid >> 1;
    const int wn   = kwid & 1;
    const int m0 = blockIdx.y * 128;
    const int n0 = blockIdx.x * 128;

    uint32_t sbase = smem_u32(smem);

    const int rA     = (lane & 7) + ((lane >> 3) & 1) * 8;
    const int kbyteA = ((lane >> 4) & 1) * 16;
    uint32_t aOff = (uint32_t)(wm * 32 + rA) * PITCHB + kbyteA;

    const int rB     = (lane & 7) + ((lane >> 4) & 1) * 8;
    const int kbyteB = ((lane >> 3) & 1) * 16;
    uint32_t bOff = (uint32_t)(1 + grp) * A_TILE_BYTES
                  + (uint32_t)(wn * 64 + rB) * PITCHB + kbyteB;

    float acc[2][8][4];
    #pragma unroll
    for (int mt = 0; mt < 2; mt++)
        #pragma unroll
        for (int nt = 0; nt < 8; nt++)
            #pragma unroll
            for (int r = 0; r < 4; r++) acc[mt][nt][r] = 0.f;

    auto issue3 = [&](int stage, int k0) {
        uint32_t sA = sbase + stage * STAGE3_BYTES;
        #pragma unroll
        for (int i = 0; i < 2; i++) {
            int f   = tid + i * 512;
            int row = f >> 3;
            int c   = f & 7;
            uint32_t soff = (uint32_t)row * PITCHB + c * 16;
            CP_ASYNC16(sA + soff, A + (size_t)(m0 + row) * CC + k0 + c * 8);
            CP_ASYNC16(sA + A_TILE_BYTES + soff,
                       Wk + (size_t)(n0 + row) * CC + k0 + c * 8);
            CP_ASYNC16(sA + 2 * A_TILE_BYTES + soff,
                       Wv + (size_t)(n0 + row) * CC + k0 + c * 8);
        }
        CP_COMMIT();
    };

    issue3(0, 0);
    issue3(1, 64);

    int stage = 0;
    #pragma unroll 1
    for (int it = 0; it < NITER; it++) {
        CP_WAIT1();
        __syncthreads();
        if (it + 2 < NITER) {
            int ns = stage + 2; if (ns >= 3) ns -= 3;
            issue3(ns, (it + 2) * 64);
        } else {
            CP_COMMIT();
        }

        uint32_t sstage = sbase + stage * STAGE3_BYTES;

        #pragma unroll
        for (int s = 0; s < 4; s++) {
            uint32_t sb = sstage + s * 32;
            uint32_t af[8];
            LDSM_X4(af[0], af[1], af[2], af[3], sb + aOff);
            LDSM_X4(af[4], af[5], af[6], af[7], sb + aOff + 16 * PITCHB);
            #pragma unroll
            for (int p = 0; p < 4; p++) {
                uint32_t bf[4];
                LDSM_X4(bf[0], bf[1], bf[2], bf[3],
                        sb + bOff + (uint32_t)p * (16 * PITCHB));
                mma_f16(acc[0][2*p    ], af,     bf);
                mma_f16(acc[0][2*p + 1], af,     bf + 2);
                mma_f16(acc[1][2*p    ], af + 4, bf);
                mma_f16(acc[1][2*p + 1], af + 4, bf + 2);
            }
        }
        stage++; if (stage >= 3) stage -= 3;
    }
    __syncthreads();

    const uint32_t svb = sbase;
    const uint32_t skb = sbase + 128 * KVPITCH;
    const float* bias = grp ? bv : bk;
    char* tilebase = smem + (grp ? 0 : 128 * KVPITCH);

    const int ncol0 = n0 + wn * 64;
    #pragma unroll
    for (int mt = 0; mt < 2; mt++) {
        #pragma unroll
        for (int half = 0; half < 2; half++) {
            int rloc = wm * 32 + mt * 16 + g + half * 8;
            float v[16];
            #pragma unroll
            for (int nt = 0; nt < 8; nt++) {
                int col = ncol0 + nt * 8 + tig * 2;
                v[nt * 2 + 0] = acc[mt][nt][half * 2 + 0] + __ldg(bias + col);
                v[nt * 2 + 1] = acc[mt][nt][half * 2 + 1] + __ldg(bias + col + 1);
            }
            if (grp == 0) {
                float mx = v[0];
                #pragma unroll
                for (int j = 1; j < 16; j++) mx = fmaxf(mx, v[j]);
                mx = fmaxf(mx, __shfl_xor_sync(0xffffffffu, mx, 1));
                mx = fmaxf(mx, __shfl_xor_sync(0xffffffffu, mx, 2));
                float s = 0.f;
                #pragma unroll
                for (int j = 0; j < 16; j++) { v[j] = __expf(v[j] - mx); s += v[j]; }
                s += __shfl_xor_sync(0xffffffffu, s, 1);
                s += __shfl_xor_sync(0xffffffffu, s, 2);
                float inv = 1.f / s;
                #pragma unroll
                for (int j = 0; j < 16; j++) v[j] *= inv;
            }
            char* dst = tilebase + (uint32_t)rloc * KVPITCH;
            #pragma unroll
            for (int nt = 0; nt < 8; nt++)
                *(__half2*)(dst + (wn * 64 + nt * 8 + tig * 2) * 2) =
                    __floats2half2_rn(v[nt * 2], v[nt * 2 + 1]);
        }
    }
    __syncthreads();

    if (grp == 0) {
        const int hh = wid >> 2;
        const int d0 = (wid & 3) * 16;
        const int bh = (m0 >> 12) * HH + (n0 >> 6) + hh;

        float accv[8][4];
        #pragma unroll
        for (int i = 0; i < 8; i++)
            #pragma unroll
            for (int r = 0; r < 4; r++) accv[i][r] = 0.f;

        uint32_t aAddr = skb + (uint32_t)((lane & 7) + ((lane >> 4) & 1) * 8) * KVPITCH
                       + (hh * 64 + d0 + ((lane >> 3) & 1) * 8) * 2;
        uint32_t bAddr = svb + (uint32_t)((lane & 7) + ((lane >> 3) & 1) * 8) * KVPITCH
                       + (hh * 64 + ((lane >> 4) & 1) * 8) * 2;

        #pragma unroll
        for (int k0 = 0; k0 < 128; k0 += 16) {
            uint32_t af[4];
            LDSM_X4_T(af[0], af[1], af[2], af[3], aAddr + (uint32_t)k0 * KVPITCH);
            #pragma unroll
            for (int et = 0; et < 4; et++) {
                uint32_t bf[4];
                LDSM_X4_T(bf[0], bf[1], bf[2], bf[3],
                          bAddr + (uint32_t)k0 * KVPITCH + et * 32);
                mma_f16(accv[et * 2    ], af, bf);
                mma_f16(accv[et * 2 + 1], af, bf + 2);
            }
        }

        #pragma unroll
        for (int et = 0; et < 4; et++)
            #pragma unroll
            for (int nn = 0; nn < 2; nn++)
                #pragma unroll
                for (int half = 0; half < 2; half++) {
                    int d = d0 + g + half * 8;
                    int e = et * 16 + nn * 8 + tig * 2;
                    float* base = kv_out + ((size_t)bh * 64 + d) * 64 + e;
                    atomicAdd(base    , accv[et * 2 + nn][half * 2 + 0]);
                    atomicAdd(base + 1, accv[et * 2 + nn][half * 2 + 1]);
                }
    } else {
        int t2 = tid - 256;
        int c  = t2 & 127;
        int r0 = (t2 >> 7) * 64;
        float s = 0.f;
        #pragma unroll 8
        for (int r = 0; r < 64; r++)
            s += __half2float(*(const __half*)(smem + 128 * KVPITCH +
                    (uint32_t)(r0 + r) * KVPITCH + c * 2));
        atomicAdd(&ksum_out[(m0 >> 12) * CC + n0 + c], s);
    }
}

// ============================================================================
// Q / P GEMM: 128 threads, 4 warps, warp tile 64x64 (128 acc regs/thread),
// 2 CTAs/SM (256-reg cap). MODE 2 = Q (softmax + combine), MODE 3 = P (fp32).
// Per k16-step: 8 LDSM : 32 HMMA (was 6:16).
// ============================================================================
__device__ __forceinline__ void issue_copy(const __half* __restrict__ A,
                                           const __half* __restrict__ W,
                                           uint32_t sbase, int stage,
                                           int m0, int n0, int k0, int tid)
{
    uint32_t sA = sbase + stage * STAGE_BYTES;
    uint32_t sW = sA + A_TILE_BYTES;
    #pragma unroll
    for (int i = 0; i < 8; i++) {
        int f   = tid + i * 128;      // 0..1023 chunks per tile
        int row = f >> 3;
        int c   = f & 7;
        uint32_t soff = (uint32_t)row * PITCHB + c * 16;
        CP_ASYNC16(sA + soff, A + (size_t)(m0 + row) * CC + k0 + c * 8);
        CP_ASYNC16(sW + soff, W + (size_t)(n0 + row) * CC + k0 + c * 8);
    }
    CP_COMMIT();
}

template<int MODE>
__global__ __launch_bounds__(128, 2)
void gemm_mma(const __half* __restrict__ A, const __half* __restrict__ W,
              const float* __restrict__ bias, void* __restrict__ Cmat,
              const float* __restrict__ kvp, const float* __restrict__ ksump)
{
    constexpr bool FUSE   = (MODE == 2);
    constexpr bool OUTF32 = (MODE == 3);

    extern __shared__ char smem[];
    const int tid  = threadIdx.x;
    const int wid  = tid >> 5;      // 0..3
    const int lane = tid & 31;
    const int g    = lane >> 2;
    const int tig  = lane & 3;
    const int wm   = wid >> 1;      // rows [wm*64, +64)
    const int wn   = wid & 1;       // cols [wn*64, +64)
    const int m0 = blockIdx.y * 128;
    const int n0 = blockIdx.x * 128;

    uint32_t sbase = smem_u32(smem);

    const int rA     = (lane & 7) + ((lane >> 3) & 1) * 8;
    const int kbyteA = ((lane >> 4) & 1) * 16;
    uint32_t aOff = (uint32_t)(wm * 64 + rA) * PITCHB + kbyteA;

    const int rB     = (lane & 7) + ((lane >> 4) & 1) * 8;
    const int kbyteB = ((lane >> 3) & 1) * 16;
    uint32_t bOff = A_TILE_BYTES + (uint32_t)(wn * 64 + rB) * PITCHB + kbyteB;

    float acc[4][8][4];
    #pragma unroll
    for (int mt = 0; mt < 4; mt++)
        #pragma unroll
        for (int nt = 0; nt < 8; nt++)
            #pragma unroll
            for (int r = 0; r < 4; r++) acc[mt][nt][r] = 0.f;

    issue_copy(A, W, sbase, 0, m0, n0, 0, tid);
    issue_copy(A, W, sbase, 1, m0, n0, 64, tid);

    int stage = 0;
    #pragma unroll 1
    for (int it = 0; it < NITER; it++) {
        CP_WAIT1();
        __syncthreads();
        if (it + 2 < NITER) {
            int ns = stage + 2; if (ns >= 3) ns -= 3;
            issue_copy(A, W, sbase, ns, m0, n0, (it + 2) * 64, tid);
        } else {
            CP_COMMIT();
        }

        uint32_t sstage = sbase + stage * STAGE_BYTES;

        #pragma unroll
        for (int s = 0; s < 4; s++) {
            uint32_t sb = sstage + s * 32;
            uint32_t af[16], bf[16];
            #pragma unroll
            for (int mt = 0; mt < 4; mt++)
                LDSM_X4(af[mt*4], af[mt*4+1], af[mt*4+2], af[mt*4+3],
                        sb + aOff + (uint32_t)mt * (16 * PITCHB));
            #pragma unroll
            for (int p = 0; p < 4; p++)
                LDSM_X4(bf[p*4], bf[p*4+1], bf[p*4+2], bf[p*4+3],
                        sb + bOff + (uint32_t)p * (16 * PITCHB));
            #pragma unroll
            for (int mt = 0; mt < 4; mt++)
                #pragma unroll
                for (int p = 0; p < 4; p++) {
                    mma_f16(acc[mt][2*p    ], af + mt*4, bf + p*4);
                    mma_f16(acc[mt][2*p + 1], af + mt*4, bf + p*4 + 2);
                }
        }
        stage++; if (stage >= 3) stage -= 3;
    }
    __syncthreads();

    float* smemf = (float*)smem;
    if (FUSE) {
        int b  = m0 >> 12;
        int h0 = n0 >> 6;
        const float* kvg = kvp + ((size_t)(b * HH + h0) << 12);
        #pragma unroll
        for (int i = 0; i < 16; i++) {
            int idx = tid + i * 128;
            *(float4*)&smemf[idx * 4] = *(const float4*)(kvg + idx * 4);
        }
        if (tid < 32)
            *(float4*)&smemf[8192 + tid * 4] =
                *(const float4*)(ksump + (m0 >> 12) * CC + (h0 << 6) + tid * 4);
        __syncthreads();
    }

    const int ncol0 = n0 + wn * 64;
    #pragma unroll
    for (int mt = 0; mt < 4; mt++) {
        #pragma unroll
        for (int half = 0; half < 2; half++) {
            int row = m0 + wm * 64 + mt * 16 + g + half * 8;
            float v[16];
            #pragma unroll
            for (int nt = 0; nt < 8; nt++) {
                int col = ncol0 + nt * 8 + tig * 2;
                v[nt * 2 + 0] = acc[mt][nt][half * 2 + 0] + __ldg(bias + col);
                v[nt * 2 + 1] = acc[mt][nt][half * 2 + 1] + __ldg(bias + col + 1);
            }
            if (FUSE) {
                float mx = v[0];
                #pragma unroll
                for (int j = 1; j < 16; j++) mx = fmaxf(mx, v[j]);
                mx = fmaxf(mx, __shfl_xor_sync(0xffffffffu, mx, 1));
                mx = fmaxf(mx, __shfl_xor_sync(0xffffffffu, mx, 2));
                float s = 0.f;
                #pragma unroll
                for (int j = 0; j < 16; j++) { v[j] = __expf(v[j] - mx); s += v[j]; }
                s += __shfl_xor_sync(0xffffffffu, s, 1);
                s += __shfl_xor_sync(0xffffffffu, s, 2);
                float inv = 1.f / s;
                #pragma unroll
                for (int j = 0; j < 16; j++) v[j] *= inv;

                const float* kv_s  = smemf + wn * 4096;
                const float* kss_s = smemf + 8192 + wn * 64;
                float acc2[16];
                #pragma unroll
                for (int j = 0; j < 16; j++) acc2[j] = 0.f;
                float dsum = 0.f;
                #pragma unroll
                for (int r = 0; r < 4; r++) {
                    #pragma unroll
                    for (int j = 0; j < 16; j++) {
                        float qd = __shfl_sync(0xffffffffu, v[j], r, 4);
                        int d = ((j >> 1) << 3) + (r << 1) + (j & 1);
                        dsum += qd * kss_s[d];
                        const float* kvr = kv_s + (d << 6) + (tig << 1);
                        #pragma unroll
                        for (int nt2 = 0; nt2 < 8; nt2++) {
                            float2 kvv = *(const float2*)(kvr + (nt2 << 3));
                            acc2[nt2 * 2 + 0] += qd * kvv.x;
                            acc2[nt2 * 2 + 1] += qd * kvv.y;
                        }
                    }
                }
                float dinv = 1.f / dsum;
                #pragma unroll
                for (int j = 0; j < 16; j++) v[j] += acc2[j] * dinv;
            }
            if (OUTF32) {
                float* op = (float*)Cmat + (size_t)row * CC + ncol0 + tig * 2;
                #pragma unroll
                for (int nt = 0; nt < 8; nt++)
                    *(float2*)(op + nt * 8) = make_float2(v[nt * 2], v[nt * 2 + 1]);
            } else {
                __half* op = (__half*)Cmat + (size_t)row * CC + ncol0 + tig * 2;
                #pragma unroll
                for (int nt = 0; nt < 8; nt++)
                    *(__half2*)(op + nt * 8) = __floats2half2_rn(v[nt * 2], v[nt * 2 + 1]);
            }
        }
    }
}

// ============================================================================
// mega-prep (unchanged from R11)
// ============================================================================
__device__ __forceinline__ void cvt8(const float* __restrict__ src,
                                     __half* __restrict__ dst, int i)
{
    float4 a = *(const float4*)(src + (size_t)i * 8);
    float4 b = *(const float4*)(src + (size_t)i * 8 + 4);
    __half2 h0 = __floats2half2_rn(a.x, a.y);
    __half2 h1 = __floats2half2_rn(a.z, a.w);
    __half2 h2 = __floats2half2_rn(b.x, b.y);
    __half2 h3 = __floats2half2_rn(b.z, b.w);
    uint4 r;
    r.x = *(uint32_t*)&h0; r.y = *(uint32_t*)&h1;
    r.z = *(uint32_t*)&h2; r.w = *(uint32_t*)&h3;
    *(uint4*)(dst + (size_t)i * 8) = r;
}

__global__ void prep_kernel(const float* y, const float* x,
                            const float* w0, const float* w1,
                            const float* w2, const float* w3,
                            __half* yc, __half* xc,
                            __half* d0, __half* d1, __half* d2, __half* d3,
                            float* kvz, float* ksz)
{
    int b = blockIdx.x;
    int t = threadIdx.x;
    if (b < 8192) {
        cvt8(y, yc, b * 256 + t);
    } else if (b < 16384) {
        cvt8(x, xc, (b - 8192) * 256 + t);
    } else if (b < 18432) {
        int w = (b - 16384) >> 9;
        int i = ((b - 16384) & 511) * 256 + t;
        const float* s; __half* d;
        switch (w) {
            case 0:  s = w0; d = d0; break;
            case 1:  s = w1; d = d1; break;
            case 2:  s = w2; d = d2; break;
            default: s = w3; d = d3; break;
        }
        cvt8(s, d, i);
    } else {
        int i = (b - 18432) * 256 + t;
        *(float4*)(kvz + (size_t)i * 4) = make_float4(0.f, 0.f, 0.f, 0.f);
        if (i < 1024)
            *(float4*)(ksz + (size_t)i * 4) = make_float4(0.f, 0.f, 0.f, 0.f);
    }
}

// ============================================================================
// Launch: 4 kernels (prep, KV, Q, P); #4 (P) is the one ncu profiles
// ============================================================================
extern "C" void kernel_launch(void* const* d_in, const int* in_sizes, int n_in,
                              void* d_out, int out_size)
{
    const float* x  = (const float*)d_in[0];
    const float* y  = (const float*)d_in[1];
    const float* Wq = (const float*)d_in[2];
    const float* bq = (const float*)d_in[3];
    const float* Wk = (const float*)d_in[4];
    const float* bk = (const float*)d_in[5];
    const float* Wv = (const float*)d_in[6];
    const float* bv = (const float*)d_in[7];
    const float* Wp = (const float*)d_in[8];
    const float* bp = (const float*)d_in[9];
    float* out = (float*)d_out;

    __half *attn, *xc, *yc, *wqc, *wkc, *wvc, *wpc;
    float *ksum, *kv;
    cudaGetSymbolAddress((void**)&attn, g_attn);
    cudaGetSymbolAddress((void**)&xc,   g_xc);
    cudaGetSymbolAddress((void**)&yc,   g_yc);
    cudaGetSymbolAddress((void**)&wqc,  g_wqc);
    cudaGetSymbolAddress((void**)&wkc,  g_wkc);
    cudaGetSymbolAddress((void**)&wvc,  g_wvc);
    cudaGetSymbolAddress((void**)&wpc,  g_wpc);
    cudaGetSymbolAddress((void**)&ksum, g_ksum);
    cudaGetSymbolAddress((void**)&kv,   g_kv);

    cudaFuncSetAttribute(gemm_kv,     cudaFuncAttributeMaxDynamicSharedMemorySize, KV_SMEM);
    cudaFuncSetAttribute(gemm_mma<2>, cudaFuncAttributeMaxDynamicSharedMemorySize, GEMM_SMEM);
    cudaFuncSetAttribute(gemm_mma<3>, cudaFuncAttributeMaxDynamicSharedMemorySize, GEMM_SMEM);

    dim3 ggrid(CC / 128, MM / 128);  // (8, 128)

    // 1: prep (cvt x, y, weights; zero kv/ksum)
    prep_kernel<<<18688, 256>>>(y, x, Wk, Wv, Wq, Wp,
                                yc, xc, wkc, wvc, wqc, wpc, kv, ksum);
    // 2: merged K+V GEMM -> kv, ksum
    gemm_kv<<<ggrid, 512, KV_SMEM>>>(yc, wkc, wvc, bk, bv, kv, ksum);
    // 3: Q-GEMM with fused softmax + combine -> attn (fp16)
    gemm_mma<2><<<ggrid, 128, GEMM_SMEM>>>(xc, wqc, bq, attn, kv, ksum);
    // 4: output projection -> fp32 out (profiled)
    gemm_mma<3><<<ggrid, 128, GEMM_SMEM>>>(attn, wpc, bp, out, nullptr, nullptr);
}

// round 14
// speedup vs baseline: 1.1161x; 1.1161x over previous
#include <cuda_runtime.h>
#include <cuda_fp16.h>
#include <cstdint>

#define BB 4
#define TT 4096
#define CC 1024
#define HH 16
#define DD 64
#define MM (BB*TT)   // 16384

// Scratch (device globals — no allocation allowed)
__device__ __half g_attn[(size_t)MM*CC];
__device__ __half g_xc[(size_t)MM*CC];
__device__ __half g_yc[(size_t)MM*CC];
__device__ __half g_wqc[CC*CC];
__device__ __half g_wkc[CC*CC];
__device__ __half g_wvc[CC*CC];
__device__ __half g_wpc[CC*CC];
__device__ float  g_ksum[BB*CC];
__device__ float  g_kv[BB*HH*DD*DD];

__device__ __forceinline__ uint32_t smem_u32(const void* p) {
    uint32_t a;
    asm("{ .reg .u64 t; cvta.to.shared.u64 t, %1; cvt.u32.u64 %0, t; }" : "=r"(a) : "l"(p));
    return a;
}

#define CP_ASYNC16(saddr, gptr) \
    asm volatile("cp.async.cg.shared.global [%0], [%1], 16;" :: "r"(saddr), "l"(gptr))
#define CP_COMMIT() asm volatile("cp.async.commit_group;" ::: "memory")
#define CP_WAIT1()  asm volatile("cp.async.wait_group 1;" ::: "memory")

__device__ __forceinline__ void mma_f16(float* c, const uint32_t* a, const uint32_t* b) {
    asm volatile(
        "mma.sync.aligned.m16n8k16.row.col.f32.f16.f16.f32 "
        "{%0,%1,%2,%3}, {%4,%5,%6,%7}, {%8,%9}, {%0,%1,%2,%3};"
        : "+f"(c[0]), "+f"(c[1]), "+f"(c[2]), "+f"(c[3])
        : "r"(a[0]), "r"(a[1]), "r"(a[2]), "r"(a[3]), "r"(b[0]), "r"(b[1]));
}

#define LDSM_X4(r0, r1, r2, r3, addr) \
    asm volatile("ldmatrix.sync.aligned.m8n8.x4.shared.b16 {%0,%1,%2,%3}, [%4];" \
                 : "=r"(r0), "=r"(r1), "=r"(r2), "=r"(r3) : "r"(addr))
#define LDSM_X4_T(r0, r1, r2, r3, addr) \
    asm volatile("ldmatrix.sync.aligned.m8n8.x4.trans.shared.b16 {%0,%1,%2,%3}, [%4];" \
                 : "=r"(r0), "=r"(r1), "=r"(r2), "=r"(r3) : "r"(addr))

#define PITCHB 144
#define A_TILE_BYTES (128*PITCHB)      // 18432
#define STAGE_BYTES (2*A_TILE_BYTES)   // 36864   (Q kernel)
#define GEMM_SMEM (3*STAGE_BYTES)      // 110592
#define STAGE3_BYTES (3*A_TILE_BYTES)  // 55296   (KV kernel)
#define KV_SMEM (3*STAGE3_BYTES)       // 165888
#define NITER 16
#define KVPITCH 272                    // epilogue tile pitch (136 halfs)

// P-GEMM (BM=256, BN=128) tiles
#define P_A_TILE (256*PITCHB)          // 36864
#define P_STAGE (P_A_TILE + 128*PITCHB)// 55296
#define P_SMEM (3*P_STAGE)             // 165888

// ============================================================================
// KV mega-kernel (512 threads) — unchanged from R11
// ============================================================================
__global__ __launch_bounds__(512, 1)
void gemm_kv(const __half* __restrict__ A,
             const __half* __restrict__ Wk, const __half* __restrict__ Wv,
             const float* __restrict__ bk, const float* __restrict__ bv,
             float* __restrict__ kv_out, float* __restrict__ ksum_out)
{
    extern __shared__ char smem[];
    const int tid  = threadIdx.x;
    const int wid  = tid >> 5;
    const int lane = tid & 31;
    const int g    = lane >> 2;
    const int tig  = lane & 3;
    const int grp  = wid >> 3;        // 0 = K, 1 = V
    const int kwid = wid & 7;
    const int wm   = kwid >> 1;
    const int wn   = kwid & 1;
    const int m0 = blockIdx.y * 128;
    const int n0 = blockIdx.x * 128;

    uint32_t sbase = smem_u32(smem);

    const int rA     = (lane & 7) + ((lane >> 3) & 1) * 8;
    const int kbyteA = ((lane >> 4) & 1) * 16;
    uint32_t aOff = (uint32_t)(wm * 32 + rA) * PITCHB + kbyteA;

    const int rB     = (lane & 7) + ((lane >> 4) & 1) * 8;
    const int kbyteB = ((lane >> 3) & 1) * 16;
    uint32_t bOff = (uint32_t)(1 + grp) * A_TILE_BYTES
                  + (uint32_t)(wn * 64 + rB) * PITCHB + kbyteB;

    float acc[2][8][4];
    #pragma unroll
    for (int mt = 0; mt < 2; mt++)
        #pragma unroll
        for (int nt = 0; nt < 8; nt++)
            #pragma unroll
            for (int r = 0; r < 4; r++) acc[mt][nt][r] = 0.f;

    auto issue3 = [&](int stage, int k0) {
        uint32_t sA = sbase + stage * STAGE3_BYTES;
        #pragma unroll
        for (int i = 0; i < 2; i++) {
            int f   = tid + i * 512;
            int row = f >> 3;
            int c   = f & 7;
            uint32_t soff = (uint32_t)row * PITCHB + c * 16;
            CP_ASYNC16(sA + soff, A + (size_t)(m0 + row) * CC + k0 + c * 8);
            CP_ASYNC16(sA + A_TILE_BYTES + soff,
                       Wk + (size_t)(n0 + row) * CC + k0 + c * 8);
            CP_ASYNC16(sA + 2 * A_TILE_BYTES + soff,
                       Wv + (size_t)(n0 + row) * CC + k0 + c * 8);
        }
        CP_COMMIT();
    };

    issue3(0, 0);
    issue3(1, 64);

    int stage = 0;
    #pragma unroll 1
    for (int it = 0; it < NITER; it++) {
        CP_WAIT1();
        __syncthreads();
        if (it + 2 < NITER) {
            int ns = stage + 2; if (ns >= 3) ns -= 3;
            issue3(ns, (it + 2) * 64);
        } else {
            CP_COMMIT();
        }

        uint32_t sstage = sbase + stage * STAGE3_BYTES;

        #pragma unroll
        for (int s = 0; s < 4; s++) {
            uint32_t sb = sstage + s * 32;
            uint32_t af[8];
            LDSM_X4(af[0], af[1], af[2], af[3], sb + aOff);
            LDSM_X4(af[4], af[5], af[6], af[7], sb + aOff + 16 * PITCHB);
            #pragma unroll
            for (int p = 0; p < 4; p++) {
                uint32_t bf[4];
                LDSM_X4(bf[0], bf[1], bf[2], bf[3],
                        sb + bOff + (uint32_t)p * (16 * PITCHB));
                mma_f16(acc[0][2*p    ], af,     bf);
                mma_f16(acc[0][2*p + 1], af,     bf + 2);
                mma_f16(acc[1][2*p    ], af + 4, bf);
                mma_f16(acc[1][2*p + 1], af + 4, bf + 2);
            }
        }
        stage++; if (stage >= 3) stage -= 3;
    }
    __syncthreads();

    const uint32_t svb = sbase;
    const uint32_t skb = sbase + 128 * KVPITCH;
    const float* bias = grp ? bv : bk;
    char* tilebase = smem + (grp ? 0 : 128 * KVPITCH);

    const int ncol0 = n0 + wn * 64;
    #pragma unroll
    for (int mt = 0; mt < 2; mt++) {
        #pragma unroll
        for (int half = 0; half < 2; half++) {
            int rloc = wm * 32 + mt * 16 + g + half * 8;
            float v[16];
            #pragma unroll
            for (int nt = 0; nt < 8; nt++) {
                int col = ncol0 + nt * 8 + tig * 2;
                v[nt * 2 + 0] = acc[mt][nt][half * 2 + 0] + __ldg(bias + col);
                v[nt * 2 + 1] = acc[mt][nt][half * 2 + 1] + __ldg(bias + col + 1);
            }
            if (grp == 0) {
                float mx = v[0];
                #pragma unroll
                for (int j = 1; j < 16; j++) mx = fmaxf(mx, v[j]);
                mx = fmaxf(mx, __shfl_xor_sync(0xffffffffu, mx, 1));
                mx = fmaxf(mx, __shfl_xor_sync(0xffffffffu, mx, 2));
                float s = 0.f;
                #pragma unroll
                for (int j = 0; j < 16; j++) { v[j] = __expf(v[j] - mx); s += v[j]; }
                s += __shfl_xor_sync(0xffffffffu, s, 1);
                s += __shfl_xor_sync(0xffffffffu, s, 2);
                float inv = 1.f / s;
                #pragma unroll
                for (int j = 0; j < 16; j++) v[j] *= inv;
            }
            char* dst = tilebase + (uint32_t)rloc * KVPITCH;
            #pragma unroll
            for (int nt = 0; nt < 8; nt++)
                *(__half2*)(dst + (wn * 64 + nt * 8 + tig * 2) * 2) =
                    __floats2half2_rn(v[nt * 2], v[nt * 2 + 1]);
        }
    }
    __syncthreads();

    if (grp == 0) {
        const int hh = wid >> 2;
        const int d0 = (wid & 3) * 16;
        const int bh = (m0 >> 12) * HH + (n0 >> 6) + hh;

        float accv[8][4];
        #pragma unroll
        for (int i = 0; i < 8; i++)
            #pragma unroll
            for (int r = 0; r < 4; r++) accv[i][r] = 0.f;

        uint32_t aAddr = skb + (uint32_t)((lane & 7) + ((lane >> 4) & 1) * 8) * KVPITCH
                       + (hh * 64 + d0 + ((lane >> 3) & 1) * 8) * 2;
        uint32_t bAddr = svb + (uint32_t)((lane & 7) + ((lane >> 3) & 1) * 8) * KVPITCH
                       + (hh * 64 + ((lane >> 4) & 1) * 8) * 2;

        #pragma unroll
        for (int k0 = 0; k0 < 128; k0 += 16) {
            uint32_t af[4];
            LDSM_X4_T(af[0], af[1], af[2], af[3], aAddr + (uint32_t)k0 * KVPITCH);
            #pragma unroll
            for (int et = 0; et < 4; et++) {
                uint32_t bf[4];
                LDSM_X4_T(bf[0], bf[1], bf[2], bf[3],
                          bAddr + (uint32_t)k0 * KVPITCH + et * 32);
                mma_f16(accv[et * 2    ], af, bf);
                mma_f16(accv[et * 2 + 1], af, bf + 2);
            }
        }

        #pragma unroll
        for (int et = 0; et < 4; et++)
            #pragma unroll
            for (int nn = 0; nn < 2; nn++)
                #pragma unroll
                for (int half = 0; half < 2; half++) {
                    int d = d0 + g + half * 8;
                    int e = et * 16 + nn * 8 + tig * 2;
                    float* base = kv_out + ((size_t)bh * 64 + d) * 64 + e;
                    atomicAdd(base    , accv[et * 2 + nn][half * 2 + 0]);
                    atomicAdd(base + 1, accv[et * 2 + nn][half * 2 + 1]);
                }
    } else {
        int t2 = tid - 256;
        int c  = t2 & 127;
        int r0 = (t2 >> 7) * 64;
        float s = 0.f;
        #pragma unroll 8
        for (int r = 0; r < 64; r++)
            s += __half2float(*(const __half*)(smem + 128 * KVPITCH +
                    (uint32_t)(r0 + r) * KVPITCH + c * 2));
        atomicAdd(&ksum_out[(m0 >> 12) * CC + n0 + c], s);
    }
}

// ============================================================================
// Q-GEMM (R11 shape: 256 threads, warp tile 32x64, 2 CTAs/SM)
// fused softmax + linear-attention combine, fp16 out
// ============================================================================
__device__ __forceinline__ void issue_copy(const __half* __restrict__ A,
                                           const __half* __restrict__ W,
                                           uint32_t sbase, int stage,
                                           int m0, int n0, int k0, int tid)
{
    uint32_t sA = sbase + stage * STAGE_BYTES;
    uint32_t sW = sA + A_TILE_BYTES;
    #pragma unroll
    for (int i = 0; i < 4; i++) {
        int f   = tid + i * 256;
        int row = f >> 3;
        int c   = f & 7;
        uint32_t soff = (uint32_t)row * PITCHB + c * 16;
        CP_ASYNC16(sA + soff, A + (size_t)(m0 + row) * CC + k0 + c * 8);
        CP_ASYNC16(sW + soff, W + (size_t)(n0 + row) * CC + k0 + c * 8);
    }
    CP_COMMIT();
}

__global__ __launch_bounds__(256, 2)
void gemm_q(const __half* __restrict__ A, const __half* __restrict__ W,
            const float* __restrict__ bias, __half* __restrict__ Cmat,
            const float* __restrict__ kvp, const float* __restrict__ ksump)
{
    extern __shared__ char smem[];
    const int tid  = threadIdx.x;
    const int wid  = tid >> 5;
    const int lane = tid & 31;
    const int g    = lane >> 2;
    const int tig  = lane & 3;
    const int wm   = wid >> 1;
    const int wn   = wid & 1;
    const int m0 = blockIdx.y * 128;
    const int n0 = blockIdx.x * 128;

    uint32_t sbase = smem_u32(smem);

    const int rA     = (lane & 7) + ((lane >> 3) & 1) * 8;
    const int kbyteA = ((lane >> 4) & 1) * 16;
    uint32_t aOff = (uint32_t)(wm * 32 + rA) * PITCHB + kbyteA;

    const int rB     = (lane & 7) + ((lane >> 4) & 1) * 8;
    const int kbyteB = ((lane >> 3) & 1) * 16;
    uint32_t bOff = A_TILE_BYTES + (uint32_t)(wn * 64 + rB) * PITCHB + kbyteB;

    float acc[2][8][4];
    #pragma unroll
    for (int mt = 0; mt < 2; mt++)
        #pragma unroll
        for (int nt = 0; nt < 8; nt++)
            #pragma unroll
            for (int r = 0; r < 4; r++) acc[mt][nt][r] = 0.f;

    issue_copy(A, W, sbase, 0, m0, n0, 0, tid);
    issue_copy(A, W, sbase, 1, m0, n0, 64, tid);

    int stage = 0;
    #pragma unroll 1
    for (int it = 0; it < NITER; it++) {
        CP_WAIT1();
        __syncthreads();
        if (it + 2 < NITER) {
            int ns = stage + 2; if (ns >= 3) ns -= 3;
            issue_copy(A, W, sbase, ns, m0, n0, (it + 2) * 64, tid);
        } else {
            CP_COMMIT();
        }

        uint32_t sstage = sbase + stage * STAGE_BYTES;

        #pragma unroll
        for (int s = 0; s < 4; s++) {
            uint32_t sb = sstage + s * 32;
            uint32_t af[8];
            LDSM_X4(af[0], af[1], af[2], af[3], sb + aOff);
            LDSM_X4(af[4], af[5], af[6], af[7], sb + aOff + 16 * PITCHB);
            #pragma unroll
            for (int p = 0; p < 4; p++) {
                uint32_t bf[4];
                LDSM_X4(bf[0], bf[1], bf[2], bf[3],
                        sb + bOff + (uint32_t)p * (16 * PITCHB));
                mma_f16(acc[0][2*p    ], af,     bf);
                mma_f16(acc[0][2*p + 1], af,     bf + 2);
                mma_f16(acc[1][2*p    ], af + 4, bf);
                mma_f16(acc[1][2*p + 1], af + 4, bf + 2);
            }
        }
        stage++; if (stage >= 3) stage -= 3;
    }
    __syncthreads();

    float* smemf = (float*)smem;
    {
        int b  = m0 >> 12;
        int h0 = n0 >> 6;
        const float* kvg = kvp + ((size_t)(b * HH + h0) << 12);
        #pragma unroll
        for (int i = 0; i < 8; i++) {
            int idx = tid + i * 256;
            *(float4*)&smemf[idx * 4] = *(const float4*)(kvg + idx * 4);
        }
        if (tid < 32)
            *(float4*)&smemf[8192 + tid * 4] =
                *(const float4*)(ksump + (m0 >> 12) * CC + (h0 << 6) + tid * 4);
        __syncthreads();
    }

    const int ncol0 = n0 + wn * 64;
    #pragma unroll
    for (int mt = 0; mt < 2; mt++) {
        #pragma unroll
        for (int half = 0; half < 2; half++) {
            int row = m0 + wm * 32 + mt * 16 + g + half * 8;
            float v[16];
            #pragma unroll
            for (int nt = 0; nt < 8; nt++) {
                int col = ncol0 + nt * 8 + tig * 2;
                v[nt * 2 + 0] = acc[mt][nt][half * 2 + 0] + __ldg(bias + col);
                v[nt * 2 + 1] = acc[mt][nt][half * 2 + 1] + __ldg(bias + col + 1);
            }
            // softmax over the 64-wide head group
            float mx = v[0];
            #pragma unroll
            for (int j = 1; j < 16; j++) mx = fmaxf(mx, v[j]);
            mx = fmaxf(mx, __shfl_xor_sync(0xffffffffu, mx, 1));
            mx = fmaxf(mx, __shfl_xor_sync(0xffffffffu, mx, 2));
            float s = 0.f;
            #pragma unroll
            for (int j = 0; j < 16; j++) { v[j] = __expf(v[j] - mx); s += v[j]; }
            s += __shfl_xor_sync(0xffffffffu, s, 1);
            s += __shfl_xor_sync(0xffffffffu, s, 2);
            float inv = 1.f / s;
            #pragma unroll
            for (int j = 0; j < 16; j++) v[j] *= inv;

            // linear-attention combine via quad-shfl
            const float* kv_s  = smemf + wn * 4096;
            const float* kss_s = smemf + 8192 + wn * 64;
            float acc2[16];
            #pragma unroll
            for (int j = 0; j < 16; j++) acc2[j] = 0.f;
            float dsum = 0.f;
            #pragma unroll
            for (int r = 0; r < 4; r++) {
                #pragma unroll
                for (int j = 0; j < 16; j++) {
                    float qd = __shfl_sync(0xffffffffu, v[j], r, 4);
                    int d = ((j >> 1) << 3) + (r << 1) + (j & 1);
                    dsum += qd * kss_s[d];
                    const float* kvr = kv_s + (d << 6) + (tig << 1);
                    #pragma unroll
                    for (int nt2 = 0; nt2 < 8; nt2++) {
                        float2 kvv = *(const float2*)(kvr + (nt2 << 3));
                        acc2[nt2 * 2 + 0] += qd * kvv.x;
                        acc2[nt2 * 2 + 1] += qd * kvv.y;
                    }
                }
            }
            float dinv = 1.f / dsum;
            #pragma unroll
            for (int j = 0; j < 16; j++) v[j] += acc2[j] * dinv;

            __half* op = Cmat + (size_t)row * CC + ncol0 + tig * 2;
            #pragma unroll
            for (int nt = 0; nt < 8; nt++)
                *(__half2*)(op + nt * 8) = __floats2half2_rn(v[nt * 2], v[nt * 2 + 1]);
        }
    }
}

// ============================================================================
// P-GEMM: BM=256, BN=128, 256 threads, 8 warps, warp tile 64x64 (128 acc),
// 1 CTA/SM. Raises arithmetic intensity: 55KB L2 traffic per iter per SM
// (was 147KB) for the same MAC rate. No fused epilogue -> spill-safe.
// ============================================================================
__global__ __launch_bounds__(256, 1)
void gemm_p(const __half* __restrict__ A, const __half* __restrict__ W,
            const float* __restrict__ bias, float* __restrict__ Cmat)
{
    extern __shared__ char smem[];
    const int tid  = threadIdx.x;
    const int wid  = tid >> 5;      // 0..7
    const int lane = tid & 31;
    const int g    = lane >> 2;
    const int tig  = lane & 3;
    const int wm   = wid >> 1;      // 0..3 -> rows [wm*64, +64)
    const int wn   = wid & 1;       // cols [wn*64, +64)
    const int m0 = blockIdx.y * 256;
    const int n0 = blockIdx.x * 128;

    uint32_t sbase = smem_u32(smem);

    const int rA     = (lane & 7) + ((lane >> 3) & 1) * 8;
    const int kbyteA = ((lane >> 4) & 1) * 16;
    uint32_t aOff = (uint32_t)(wm * 64 + rA) * PITCHB + kbyteA;

    const int rB     = (lane & 7) + ((lane >> 4) & 1) * 8;
    const int kbyteB = ((lane >> 3) & 1) * 16;
    uint32_t bOff = P_A_TILE + (uint32_t)(wn * 64 + rB) * PITCHB + kbyteB;

    float acc[4][8][4];
    #pragma unroll
    for (int mt = 0; mt < 4; mt++)
        #pragma unroll
        for (int nt = 0; nt < 8; nt++)
            #pragma unroll
            for (int r = 0; r < 4; r++) acc[mt][nt][r] = 0.f;

    auto issueP = [&](int stage, int k0) {
        uint32_t sA = sbase + stage * P_STAGE;
        // A: 256 rows x 8 chunks = 2048
        #pragma unroll
        for (int i = 0; i < 8; i++) {
            int f   = tid + i * 256;
            int row = f >> 3;
            int c   = f & 7;
            CP_ASYNC16(sA + (uint32_t)row * PITCHB + c * 16,
                       A + (size_t)(m0 + row) * CC + k0 + c * 8);
        }
        // B: 128 rows x 8 chunks = 1024
        #pragma unroll
        for (int i = 0; i < 4; i++) {
            int f   = tid + i * 256;
            int row = f >> 3;
            int c   = f & 7;
            CP_ASYNC16(sA + P_A_TILE + (uint32_t)row * PITCHB + c * 16,
                       W + (size_t)(n0 + row) * CC + k0 + c * 8);
        }
        CP_COMMIT();
    };

    issueP(0, 0);
    issueP(1, 64);

    int stage = 0;
    #pragma unroll 1
    for (int it = 0; it < NITER; it++) {
        CP_WAIT1();
        __syncthreads();
        if (it + 2 < NITER) {
            int ns = stage + 2; if (ns >= 3) ns -= 3;
            issueP(ns, (it + 2) * 64);
        } else {
            CP_COMMIT();
        }

        uint32_t sstage = sbase + stage * P_STAGE;

        #pragma unroll
        for (int s = 0; s < 4; s++) {
            uint32_t sb = sstage + s * 32;
            uint32_t af[16], bf[16];
            #pragma unroll
            for (int mt = 0; mt < 4; mt++)
                LDSM_X4(af[mt*4], af[mt*4+1], af[mt*4+2], af[mt*4+3],
                        sb + aOff + (uint32_t)mt * (16 * PITCHB));
            #pragma unroll
            for (int p = 0; p < 4; p++)
                LDSM_X4(bf[p*4], bf[p*4+1], bf[p*4+2], bf[p*4+3],
                        sb + bOff + (uint32_t)p * (16 * PITCHB));
            #pragma unroll
            for (int mt = 0; mt < 4; mt++)
                #pragma unroll
                for (int p = 0; p < 4; p++) {
                    mma_f16(acc[mt][2*p    ], af + mt*4, bf + p*4);
                    mma_f16(acc[mt][2*p + 1], af + mt*4, bf + p*4 + 2);
                }
        }
        stage++; if (stage >= 3) stage -= 3;
    }

    // Epilogue: bias + fp32 store
    const int ncol0 = n0 + wn * 64;
    #pragma unroll
    for (int mt = 0; mt < 4; mt++) {
        #pragma unroll
        for (int half = 0; half < 2; half++) {
            int row = m0 + wm * 64 + mt * 16 + g + half * 8;
            float* op = Cmat + (size_t)row * CC + ncol0 + tig * 2;
            #pragma unroll
            for (int nt = 0; nt < 8; nt++) {
                int col = ncol0 + nt * 8 + tig * 2;
                float2 r;
                r.x = acc[mt][nt][half * 2 + 0] + __ldg(bias + col);
                r.y = acc[mt][nt][half * 2 + 1] + __ldg(bias + col + 1);
                *(float2*)(op + nt * 8) = r;
            }
        }
    }
}

// ============================================================================
// mega-prep (unchanged from R11)
// ============================================================================
__device__ __forceinline__ void cvt8(const float* __restrict__ src,
                                     __half* __restrict__ dst, int i)
{
    float4 a = *(const float4*)(src + (size_t)i * 8);
    float4 b = *(const float4*)(src + (size_t)i * 8 + 4);
    __half2 h0 = __floats2half2_rn(a.x, a.y);
    __half2 h1 = __floats2half2_rn(a.z, a.w);
    __half2 h2 = __floats2half2_rn(b.x, b.y);
    __half2 h3 = __floats2half2_rn(b.z, b.w);
    uint4 r;
    r.x = *(uint32_t*)&h0; r.y = *(uint32_t*)&h1;
    r.z = *(uint32_t*)&h2; r.w = *(uint32_t*)&h3;
    *(uint4*)(dst + (size_t)i * 8) = r;
}

__global__ void prep_kernel(const float* y, const float* x,
                            const float* w0, const float* w1,
                            const float* w2, const float* w3,
                            __half* yc, __half* xc,
                            __half* d0, __half* d1, __half* d2, __half* d3,
                            float* kvz, float* ksz)
{
    int b = blockIdx.x;
    int t = threadIdx.x;
    if (b < 8192) {
        cvt8(y, yc, b * 256 + t);
    } else if (b < 16384) {
        cvt8(x, xc, (b - 8192) * 256 + t);
    } else if (b < 18432) {
        int w = (b - 16384) >> 9;
        int i = ((b - 16384) & 511) * 256 + t;
        const float* s; __half* d;
        switch (w) {
            case 0:  s = w0; d = d0; break;
            case 1:  s = w1; d = d1; break;
            case 2:  s = w2; d = d2; break;
            default: s = w3; d = d3; break;
        }
        cvt8(s, d, i);
    } else {
        int i = (b - 18432) * 256 + t;
        *(float4*)(kvz + (size_t)i * 4) = make_float4(0.f, 0.f, 0.f, 0.f);
        if (i < 1024)
            *(float4*)(ksz + (size_t)i * 4) = make_float4(0.f, 0.f, 0.f, 0.f);
    }
}

// ============================================================================
// Launch: 4 kernels (prep, KV, Q, P); #4 (P, new tiling) is profiled
// ============================================================================
extern "C" void kernel_launch(void* const* d_in, const int* in_sizes, int n_in,
                              void* d_out, int out_size)
{
    const float* x  = (const float*)d_in[0];
    const float* y  = (const float*)d_in[1];
    const float* Wq = (const float*)d_in[2];
    const float* bq = (const float*)d_in[3];
    const float* Wk = (const float*)d_in[4];
    const float* bk = (const float*)d_in[5];
    const float* Wv = (const float*)d_in[6];
    const float* bv = (const float*)d_in[7];
    const float* Wp = (const float*)d_in[8];
    const float* bp = (const float*)d_in[9];
    float* out = (float*)d_out;

    __half *attn, *xc, *yc, *wqc, *wkc, *wvc, *wpc;
    float *ksum, *kv;
    cudaGetSymbolAddress((void**)&attn, g_attn);
    cudaGetSymbolAddress((void**)&xc,   g_xc);
    cudaGetSymbolAddress((void**)&yc,   g_yc);
    cudaGetSymbolAddress((void**)&wqc,  g_wqc);
    cudaGetSymbolAddress((void**)&wkc,  g_wkc);
    cudaGetSymbolAddress((void**)&wvc,  g_wvc);
    cudaGetSymbolAddress((void**)&wpc,  g_wpc);
    cudaGetSymbolAddress((void**)&ksum, g_ksum);
    cudaGetSymbolAddress((void**)&kv,   g_kv);

    cudaFuncSetAttribute(gemm_kv, cudaFuncAttributeMaxDynamicSharedMemorySize, KV_SMEM);
    cudaFuncSetAttribute(gemm_q,  cudaFuncAttributeMaxDynamicSharedMemorySize, GEMM_SMEM);
    cudaFuncSetAttribute(gemm_p,  cudaFuncAttributeMaxDynamicSharedMemorySize, P_SMEM);

    dim3 ggrid(CC / 128, MM / 128);   // (8, 128)
    dim3 pgrid(CC / 128, MM / 256);   // (8, 64)

    // 1: prep (cvt x, y, weights; zero kv/ksum)
    prep_kernel<<<18688, 256>>>(y, x, Wk, Wv, Wq, Wp,
                                yc, xc, wkc, wvc, wqc, wpc, kv, ksum);
    // 2: merged K+V GEMM -> kv, ksum
    gemm_kv<<<ggrid, 512, KV_SMEM>>>(yc, wkc, wvc, bk, bv, kv, ksum);
    // 3: Q-GEMM with fused softmax + combine -> attn (fp16)
    gemm_q<<<ggrid, 256, GEMM_SMEM>>>(xc, wqc, bq, attn, kv, ksum);
    // 4: output projection (BM=256 tiling) -> fp32 out (profiled)
    gemm_p<<<pgrid, 256, P_SMEM>>>(attn, wpc, bp, out);
}

// round 15
// speedup vs baseline: 1.1534x; 1.0334x over previous
#include <cuda_runtime.h>
#include <cuda_fp16.h>
#include <cstdint>

#define BB 4
#define TT 4096
#define CC 1024
#define HH 16
#define DD 64
#define MM (BB*TT)   // 16384

// Scratch (device globals — no allocation allowed)
__device__ __half g_attn[(size_t)MM*CC];
__device__ __half g_xc[(size_t)MM*CC];
__device__ __half g_yc[(size_t)MM*CC];
__device__ __half g_wqc[CC*CC];
__device__ __half g_wkc[CC*CC];
__device__ __half g_wvc[CC*CC];
__device__ __half g_wpc[CC*CC];
__device__ float  g_ksum[BB*CC];
__device__ float  g_kv[BB*HH*DD*DD];

__device__ __forceinline__ uint32_t smem_u32(const void* p) {
    uint32_t a;
    asm("{ .reg .u64 t; cvta.to.shared.u64 t, %1; cvt.u32.u64 %0, t; }" : "=r"(a) : "l"(p));
    return a;
}

#define CP_ASYNC16(saddr, gptr) \
    asm volatile("cp.async.cg.shared.global [%0], [%1], 16;" :: "r"(saddr), "l"(gptr))
#define CP_COMMIT() asm volatile("cp.async.commit_group;" ::: "memory")
#define CP_WAIT1()  asm volatile("cp.async.wait_group 1;" ::: "memory")

__device__ __forceinline__ void mma_f16(float* c, const uint32_t* a, const uint32_t* b) {
    asm volatile(
        "mma.sync.aligned.m16n8k16.row.col.f32.f16.f16.f32 "
        "{%0,%1,%2,%3}, {%4,%5,%6,%7}, {%8,%9}, {%0,%1,%2,%3};"
        : "+f"(c[0]), "+f"(c[1]), "+f"(c[2]), "+f"(c[3])
        : "r"(a[0]), "r"(a[1]), "r"(a[2]), "r"(a[3]), "r"(b[0]), "r"(b[1]));
}

#define LDSM_X4(r0, r1, r2, r3, addr) \
    asm volatile("ldmatrix.sync.aligned.m8n8.x4.shared.b16 {%0,%1,%2,%3}, [%4];" \
                 : "=r"(r0), "=r"(r1), "=r"(r2), "=r"(r3) : "r"(addr))
#define LDSM_X4_T(r0, r1, r2, r3, addr) \
    asm volatile("ldmatrix.sync.aligned.m8n8.x4.trans.shared.b16 {%0,%1,%2,%3}, [%4];" \
                 : "=r"(r0), "=r"(r1), "=r"(r2), "=r"(r3) : "r"(addr))

#define PITCHB 144
#define A_TILE_BYTES (128*PITCHB)      // 18432
#define STAGE_BYTES (2*A_TILE_BYTES)   // 36864   (Q/P kernel)
#define GEMM_SMEM (3*STAGE_BYTES)      // 110592
#define STAGE3_BYTES (3*A_TILE_BYTES)  // 55296   (KV kernel)
#define KV_SMEM (3*STAGE3_BYTES)       // 165888
#define NITER 16
#define KVPITCH 272                    // epilogue tile pitch (136 halfs)

// ============================================================================
// KV mega-kernel (512 threads) — R11 configuration
// ============================================================================
__global__ __launch_bounds__(512, 1)
void gemm_kv(const __half* __restrict__ A,
             const __half* __restrict__ Wk, const __half* __restrict__ Wv,
             const float* __restrict__ bk, const float* __restrict__ bv,
             float* __restrict__ kv_out, float* __restrict__ ksum_out)
{
    extern __shared__ char smem[];
    const int tid  = threadIdx.x;
    const int wid  = tid >> 5;
    const int lane = tid & 31;
    const int g    = lane >> 2;
    const int tig  = lane & 3;
    const int grp  = wid >> 3;        // 0 = K, 1 = V
    const int kwid = wid & 7;
    const int wm   = kwid >> 1;
    const int wn   = kwid & 1;
    const int m0 = blockIdx.y * 128;
    const int n0 = blockIdx.x * 128;

    uint32_t sbase = smem_u32(smem);

    const int rA     = (lane & 7) + ((lane >> 3) & 1) * 8;
    const int kbyteA = ((lane >> 4) & 1) * 16;
    uint32_t aOff = (uint32_t)(wm * 32 + rA) * PITCHB + kbyteA;

    const int rB     = (lane & 7) + ((lane >> 4) & 1) * 8;
    const int kbyteB = ((lane >> 3) & 1) * 16;
    uint32_t bOff = (uint32_t)(1 + grp) * A_TILE_BYTES
                  + (uint32_t)(wn * 64 + rB) * PITCHB + kbyteB;

    float acc[2][8][4];
    #pragma unroll
    for (int mt = 0; mt < 2; mt++)
        #pragma unroll
        for (int nt = 0; nt < 8; nt++)
            #pragma unroll
            for (int r = 0; r < 4; r++) acc[mt][nt][r] = 0.f;

    auto issue3 = [&](int stage, int k0) {
        uint32_t sA = sbase + stage * STAGE3_BYTES;
        #pragma unroll
        for (int i = 0; i < 2; i++) {
            int f   = tid + i * 512;
            int row = f >> 3;
            int c   = f & 7;
            uint32_t soff = (uint32_t)row * PITCHB + c * 16;
            CP_ASYNC16(sA + soff, A + (size_t)(m0 + row) * CC + k0 + c * 8);
            CP_ASYNC16(sA + A_TILE_BYTES + soff,
                       Wk + (size_t)(n0 + row) * CC + k0 + c * 8);
            CP_ASYNC16(sA + 2 * A_TILE_BYTES + soff,
                       Wv + (size_t)(n0 + row) * CC + k0 + c * 8);
        }
        CP_COMMIT();
    };

    issue3(0, 0);
    issue3(1, 64);

    int stage = 0;
    #pragma unroll 1
    for (int it = 0; it < NITER; it++) {
        CP_WAIT1();
        __syncthreads();
        if (it + 2 < NITER) {
            int ns = stage + 2; if (ns >= 3) ns -= 3;
            issue3(ns, (it + 2) * 64);
        } else {
            CP_COMMIT();
        }

        uint32_t sstage = sbase + stage * STAGE3_BYTES;

        #pragma unroll
        for (int s = 0; s < 4; s++) {
            uint32_t sb = sstage + s * 32;
            uint32_t af[8];
            LDSM_X4(af[0], af[1], af[2], af[3], sb + aOff);
            LDSM_X4(af[4], af[5], af[6], af[7], sb + aOff + 16 * PITCHB);
            #pragma unroll
            for (int p = 0; p < 4; p++) {
                uint32_t bf[4];
                LDSM_X4(bf[0], bf[1], bf[2], bf[3],
                        sb + bOff + (uint32_t)p * (16 * PITCHB));
                mma_f16(acc[0][2*p    ], af,     bf);
                mma_f16(acc[0][2*p + 1], af,     bf + 2);
                mma_f16(acc[1][2*p    ], af + 4, bf);
                mma_f16(acc[1][2*p + 1], af + 4, bf + 2);
            }
        }
        stage++; if (stage >= 3) stage -= 3;
    }
    __syncthreads();

    const uint32_t svb = sbase;
    const uint32_t skb = sbase + 128 * KVPITCH;
    const float* bias = grp ? bv : bk;
    char* tilebase = smem + (grp ? 0 : 128 * KVPITCH);

    const int ncol0 = n0 + wn * 64;
    #pragma unroll
    for (int mt = 0; mt < 2; mt++) {
        #pragma unroll
        for (int half = 0; half < 2; half++) {
            int rloc = wm * 32 + mt * 16 + g + half * 8;
            float v[16];
            #pragma unroll
            for (int nt = 0; nt < 8; nt++) {
                int col = ncol0 + nt * 8 + tig * 2;
                v[nt * 2 + 0] = acc[mt][nt][half * 2 + 0] + __ldg(bias + col);
                v[nt * 2 + 1] = acc[mt][nt][half * 2 + 1] + __ldg(bias + col + 1);
            }
            if (grp == 0) {
                float mx = v[0];
                #pragma unroll
                for (int j = 1; j < 16; j++) mx = fmaxf(mx, v[j]);
                mx = fmaxf(mx, __shfl_xor_sync(0xffffffffu, mx, 1));
                mx = fmaxf(mx, __shfl_xor_sync(0xffffffffu, mx, 2));
                float s = 0.f;
                #pragma unroll
                for (int j = 0; j < 16; j++) { v[j] = __expf(v[j] - mx); s += v[j]; }
                s += __shfl_xor_sync(0xffffffffu, s, 1);
                s += __shfl_xor_sync(0xffffffffu, s, 2);
                float inv = 1.f / s;
                #pragma unroll
                for (int j = 0; j < 16; j++) v[j] *= inv;
            }
            char* dst = tilebase + (uint32_t)rloc * KVPITCH;
            #pragma unroll
            for (int nt = 0; nt < 8; nt++)
                *(__half2*)(dst + (wn * 64 + nt * 8 + tig * 2) * 2) =
                    __floats2half2_rn(v[nt * 2], v[nt * 2 + 1]);
        }
    }
    __syncthreads();

    if (grp == 0) {
        const int hh = wid >> 2;
        const int d0 = (wid & 3) * 16;
        const int bh = (m0 >> 12) * HH + (n0 >> 6) + hh;

        float accv[8][4];
        #pragma unroll
        for (int i = 0; i < 8; i++)
            #pragma unroll
            for (int r = 0; r < 4; r++) accv[i][r] = 0.f;

        uint32_t aAddr = skb + (uint32_t)((lane & 7) + ((lane >> 4) & 1) * 8) * KVPITCH
                       + (hh * 64 + d0 + ((lane >> 3) & 1) * 8) * 2;
        uint32_t bAddr = svb + (uint32_t)((lane & 7) + ((lane >> 3) & 1) * 8) * KVPITCH
                       + (hh * 64 + ((lane >> 4) & 1) * 8) * 2;

        #pragma unroll
        for (int k0 = 0; k0 < 128; k0 += 16) {
            uint32_t af[4];
            LDSM_X4_T(af[0], af[1], af[2], af[3], aAddr + (uint32_t)k0 * KVPITCH);
            #pragma unroll
            for (int et = 0; et < 4; et++) {
                uint32_t bf[4];
                LDSM_X4_T(bf[0], bf[1], bf[2], bf[3],
                          bAddr + (uint32_t)k0 * KVPITCH + et * 32);
                mma_f16(accv[et * 2    ], af, bf);
                mma_f16(accv[et * 2 + 1], af, bf + 2);
            }
        }

        #pragma unroll
        for (int et = 0; et < 4; et++)
            #pragma unroll
            for (int nn = 0; nn < 2; nn++)
                #pragma unroll
                for (int half = 0; half < 2; half++) {
                    int d = d0 + g + half * 8;
                    int e = et * 16 + nn * 8 + tig * 2;
                    float* base = kv_out + ((size_t)bh * 64 + d) * 64 + e;
                    atomicAdd(base    , accv[et * 2 + nn][half * 2 + 0]);
                    atomicAdd(base + 1, accv[et * 2 + nn][half * 2 + 1]);
                }
    } else {
        int t2 = tid - 256;
        int c  = t2 & 127;
        int r0 = (t2 >> 7) * 64;
        float s = 0.f;
        #pragma unroll 8
        for (int r = 0; r < 64; r++)
            s += __half2float(*(const __half*)(smem + 128 * KVPITCH +
                    (uint32_t)(r0 + r) * KVPITCH + c * 2));
        atomicAdd(&ksum_out[(m0 >> 12) * CC + n0 + c], s);
    }
}

// ============================================================================
// Q / P GEMM — R11 configuration (256 threads, warp tile 32x64, 2 CTAs/SM)
// MODE 2 = Q (softmax + combine, fp16 out), MODE 3 = P (bias only, fp32 out)
// ============================================================================
__device__ __forceinline__ void issue_copy(const __half* __restrict__ A,
                                           const __half* __restrict__ W,
                                           uint32_t sbase, int stage,
                                           int m0, int n0, int k0, int tid)
{
    uint32_t sA = sbase + stage * STAGE_BYTES;
    uint32_t sW = sA + A_TILE_BYTES;
    #pragma unroll
    for (int i = 0; i < 4; i++) {
        int f   = tid + i * 256;
        int row = f >> 3;
        int c   = f & 7;
        uint32_t soff = (uint32_t)row * PITCHB + c * 16;
        CP_ASYNC16(sA + soff, A + (size_t)(m0 + row) * CC + k0 + c * 8);
        CP_ASYNC16(sW + soff, W + (size_t)(n0 + row) * CC + k0 + c * 8);
    }
    CP_COMMIT();
}

template<int MODE>
__global__ __launch_bounds__(256, 2)
void gemm_mma(const __half* __restrict__ A, const __half* __restrict__ W,
              const float* __restrict__ bias, void* __restrict__ Cmat,
              const float* __restrict__ kvp, const float* __restrict__ ksump)
{
    constexpr bool FUSE   = (MODE == 2);
    constexpr bool OUTF32 = (MODE == 3);

    extern __shared__ char smem[];
    const int tid  = threadIdx.x;
    const int wid  = tid >> 5;
    const int lane = tid & 31;
    const int g    = lane >> 2;
    const int tig  = lane & 3;
    const int wm   = wid >> 1;
    const int wn   = wid & 1;
    const int m0 = blockIdx.y * 128;
    const int n0 = blockIdx.x * 128;

    uint32_t sbase = smem_u32(smem);

    const int rA     = (lane & 7) + ((lane >> 3) & 1) * 8;
    const int kbyteA = ((lane >> 4) & 1) * 16;
    uint32_t aOff = (uint32_t)(wm * 32 + rA) * PITCHB + kbyteA;

    const int rB     = (lane & 7) + ((lane >> 4) & 1) * 8;
    const int kbyteB = ((lane >> 3) & 1) * 16;
    uint32_t bOff = A_TILE_BYTES + (uint32_t)(wn * 64 + rB) * PITCHB + kbyteB;

    float acc[2][8][4];
    #pragma unroll
    for (int mt = 0; mt < 2; mt++)
        #pragma unroll
        for (int nt = 0; nt < 8; nt++)
            #pragma unroll
            for (int r = 0; r < 4; r++) acc[mt][nt][r] = 0.f;

    issue_copy(A, W, sbase, 0, m0, n0, 0, tid);
    issue_copy(A, W, sbase, 1, m0, n0, 64, tid);

    int stage = 0;
    #pragma unroll 1
    for (int it = 0; it < NITER; it++) {
        CP_WAIT1();
        __syncthreads();
        if (it + 2 < NITER) {
            int ns = stage + 2; if (ns >= 3) ns -= 3;
            issue_copy(A, W, sbase, ns, m0, n0, (it + 2) * 64, tid);
        } else {
            CP_COMMIT();
        }

        uint32_t sstage = sbase + stage * STAGE_BYTES;

        #pragma unroll
        for (int s = 0; s < 4; s++) {
            uint32_t sb = sstage + s * 32;
            uint32_t af[8];
            LDSM_X4(af[0], af[1], af[2], af[3], sb + aOff);
            LDSM_X4(af[4], af[5], af[6], af[7], sb + aOff + 16 * PITCHB);
            #pragma unroll
            for (int p = 0; p < 4; p++) {
                uint32_t bf[4];
                LDSM_X4(bf[0], bf[1], bf[2], bf[3],
                        sb + bOff + (uint32_t)p * (16 * PITCHB));
                mma_f16(acc[0][2*p    ], af,     bf);
                mma_f16(acc[0][2*p + 1], af,     bf + 2);
                mma_f16(acc[1][2*p    ], af + 4, bf);
                mma_f16(acc[1][2*p + 1], af + 4, bf + 2);
            }
        }
        stage++; if (stage >= 3) stage -= 3;
    }
    __syncthreads();

    float* smemf = (float*)smem;
    if (FUSE) {
        int b  = m0 >> 12;
        int h0 = n0 >> 6;
        const float* kvg = kvp + ((size_t)(b * HH + h0) << 12);
        #pragma unroll
        for (int i = 0; i < 8; i++) {
            int idx = tid + i * 256;
            *(float4*)&smemf[idx * 4] = *(const float4*)(kvg + idx * 4);
        }
        if (tid < 32)
            *(float4*)&smemf[8192 + tid * 4] =
                *(const float4*)(ksump + (m0 >> 12) * CC + (h0 << 6) + tid * 4);
        __syncthreads();
    }

    const int ncol0 = n0 + wn * 64;
    #pragma unroll
    for (int mt = 0; mt < 2; mt++) {
        #pragma unroll
        for (int half = 0; half < 2; half++) {
            int row = m0 + wm * 32 + mt * 16 + g + half * 8;
            float v[16];
            #pragma unroll
            for (int nt = 0; nt < 8; nt++) {
                int col = ncol0 + nt * 8 + tig * 2;
                v[nt * 2 + 0] = acc[mt][nt][half * 2 + 0] + __ldg(bias + col);
                v[nt * 2 + 1] = acc[mt][nt][half * 2 + 1] + __ldg(bias + col + 1);
            }
            if (FUSE) {
                float mx = v[0];
                #pragma unroll
                for (int j = 1; j < 16; j++) mx = fmaxf(mx, v[j]);
                mx = fmaxf(mx, __shfl_xor_sync(0xffffffffu, mx, 1));
                mx = fmaxf(mx, __shfl_xor_sync(0xffffffffu, mx, 2));
                float s = 0.f;
                #pragma unroll
                for (int j = 0; j < 16; j++) { v[j] = __expf(v[j] - mx); s += v[j]; }
                s += __shfl_xor_sync(0xffffffffu, s, 1);
                s += __shfl_xor_sync(0xffffffffu, s, 2);
                float inv = 1.f / s;
                #pragma unroll
                for (int j = 0; j < 16; j++) v[j] *= inv;

                const float* kv_s  = smemf + wn * 4096;
                const float* kss_s = smemf + 8192 + wn * 64;
                float acc2[16];
                #pragma unroll
                for (int j = 0; j < 16; j++) acc2[j] = 0.f;
                float dsum = 0.f;
                #pragma unroll
                for (int r = 0; r < 4; r++) {
                    #pragma unroll
                    for (int j = 0; j < 16; j++) {
                        float qd = __shfl_sync(0xffffffffu, v[j], r, 4);
                        int d = ((j >> 1) << 3) + (r << 1) + (j & 1);
                        dsum += qd * kss_s[d];
                        const float* kvr = kv_s + (d << 6) + (tig << 1);
                        #pragma unroll
                        for (int nt2 = 0; nt2 < 8; nt2++) {
                            float2 kvv = *(const float2*)(kvr + (nt2 << 3));
                            acc2[nt2 * 2 + 0] += qd * kvv.x;
                            acc2[nt2 * 2 + 1] += qd * kvv.y;
                        }
                    }
                }
                float dinv = 1.f / dsum;
                #pragma unroll
                for (int j = 0; j < 16; j++) v[j] += acc2[j] * dinv;
            }
            if (OUTF32) {
                float* op = (float*)Cmat + (size_t)row * CC + ncol0 + tig * 2;
                #pragma unroll
                for (int nt = 0; nt < 8; nt++)
                    *(float2*)(op + nt * 8) = make_float2(v[nt * 2], v[nt * 2 + 1]);
            } else {
                __half* op = (__half*)Cmat + (size_t)row * CC + ncol0 + tig * 2;
                #pragma unroll
                for (int nt = 0; nt < 8; nt++)
                    *(__half2*)(op + nt * 8) = __floats2half2_rn(v[nt * 2], v[nt * 2 + 1]);
            }
        }
    }
}

// ============================================================================
// prep kernels (split so gemm_kv is our 4th launch -> gets profiled)
// ============================================================================
__device__ __forceinline__ void cvt8(const float* __restrict__ src,
                                     __half* __restrict__ dst, int i)
{
    float4 a = *(const float4*)(src + (size_t)i * 8);
    float4 b = *(const float4*)(src + (size_t)i * 8 + 4);
    __half2 h0 = __floats2half2_rn(a.x, a.y);
    __half2 h1 = __floats2half2_rn(a.z, a.w);
    __half2 h2 = __floats2half2_rn(b.x, b.y);
    __half2 h3 = __floats2half2_rn(b.z, b.w);
    uint4 r;
    r.x = *(uint32_t*)&h0; r.y = *(uint32_t*)&h1;
    r.z = *(uint32_t*)&h2; r.w = *(uint32_t*)&h3;
    *(uint4*)(dst + (size_t)i * 8) = r;
}

__global__ void cvt_f16_kernel(const float* __restrict__ src, __half* __restrict__ dst, int n8)
{
    int i = blockIdx.x * blockDim.x + threadIdx.x;
    if (i < n8) cvt8(src, dst, i);
}

// weights cvt (grid.y = 4) 
__global__ void cvt_w4_kernel(const float* s0, const float* s1,
                              const float* s2, const float* s3,
                              __half* d0, __half* d1, __half* d2, __half* d3, int n8)
{
    int i = blockIdx.x * blockDim.x + threadIdx.x;
    if (i >= n8) return;
    const float* s; __half* d;
    switch (blockIdx.y) {
        case 0:  s = s0; d = d0; break;
        case 1:  s = s1; d = d1; break;
        case 2:  s = s2; d = d2; break;
        default: s = s3; d = d3; break;
    }
    cvt8(s, d, i);
}

__global__ void zero2_kernel(float* __restrict__ a, int na4, float* __restrict__ b, int nb4)
{
    int i = blockIdx.x * blockDim.x + threadIdx.x;
    if (i < na4) *(float4*)(a + (size_t)i * 4) = make_float4(0.f, 0.f, 0.f, 0.f);
    if (i < nb4) *(float4*)(b + (size_t)i * 4) = make_float4(0.f, 0.f, 0.f, 0.f);
}

// ============================================================================
// Launch: 6 kernels; #4 = gemm_kv (the one ncu profiles this round)
// ============================================================================
extern "C" void kernel_launch(void* const* d_in, const int* in_sizes, int n_in,
                              void* d_out, int out_size)
{
    const float* x  = (const float*)d_in[0];
    const float* y  = (const float*)d_in[1];
    const float* Wq = (const float*)d_in[2];
    const float* bq = (const float*)d_in[3];
    const float* Wk = (const float*)d_in[4];
    const float* bk = (const float*)d_in[5];
    const float* Wv = (const float*)d_in[6];
    const float* bv = (const float*)d_in[7];
    const float* Wp = (const float*)d_in[8];
    const float* bp = (const float*)d_in[9];
    float* out = (float*)d_out;

    __half *attn, *xc, *yc, *wqc, *wkc, *wvc, *wpc;
    float *ksum, *kv;
    cudaGetSymbolAddress((void**)&attn, g_attn);
    cudaGetSymbolAddress((void**)&xc,   g_xc);
    cudaGetSymbolAddress((void**)&yc,   g_yc);
    cudaGetSymbolAddress((void**)&wqc,  g_wqc);
    cudaGetSymbolAddress((void**)&wkc,  g_wkc);
    cudaGetSymbolAddress((void**)&wvc,  g_wvc);
    cudaGetSymbolAddress((void**)&wpc,  g_wpc);
    cudaGetSymbolAddress((void**)&ksum, g_ksum);
    cudaGetSymbolAddress((void**)&kv,   g_kv);

    cudaFuncSetAttribute(gemm_kv,     cudaFuncAttributeMaxDynamicSharedMemorySize, KV_SMEM);
    cudaFuncSetAttribute(gemm_mma<2>, cudaFuncAttributeMaxDynamicSharedMemorySize, GEMM_SMEM);
    cudaFuncSetAttribute(gemm_mma<3>, cudaFuncAttributeMaxDynamicSharedMemorySize, GEMM_SMEM);

    dim3 ggrid(CC / 128, MM / 128);  // (8, 128)
    const int NBIG8 = (MM * CC) / 8; // 2M
    const int NW8   = (CC * CC) / 8; // 128K

    // 1: cvt y  (needed by KV)
    cvt_f16_kernel<<<NBIG8 / 256, 256>>>(y, yc, NBIG8);
    // 2: cvt all four weights
    cvt_w4_kernel<<<dim3(NW8 / 256, 4), 256>>>(Wk, Wv, Wq, Wp, wkc, wvc, wqc, wpc, NW8);
    // 3: zero kv + ksum  (kv: 262144 floats = 65536 f4; ksum: 4096 = 1024 f4)
    zero2_kernel<<<65536 / 256, 256>>>(kv, 65536, ksum, 1024);
    // 4: merged K+V GEMM -> kv, ksum (PROFILED this round)
    gemm_kv<<<ggrid, 512, KV_SMEM>>>(yc, wkc, wvc, bk, bv, kv, ksum);
    // 5: cvt x (needed by Q)
    cvt_f16_kernel<<<NBIG8 / 256, 256>>>(x, xc, NBIG8);
    // 6: Q-GEMM with fused softmax + combine -> attn (fp16)
    gemm_mma<2><<<ggrid, 256, GEMM_SMEM>>>(xc, wqc, bq, attn, kv, ksum);
    // 7: output projection -> fp32 out
    gemm_mma<3><<<ggrid, 256, GEMM_SMEM>>>(attn, wpc, bp, out, nullptr, nullptr);
}

// round 16
// speedup vs baseline: 1.4234x; 1.2341x over previous
#include <cuda_runtime.h>
#include <cuda_fp16.h>
#include <cstdint>

#define BB 4
#define TT 4096
#define CC 1024
#define HH 16
#define DD 64
#define MM (BB*TT)   // 16384

// Scratch (device globals — no allocation allowed)
__device__ __half g_attn[(size_t)MM*CC];
__device__ __half g_xc[(size_t)MM*CC];
__device__ __half g_yc[(size_t)MM*CC];
__device__ __half g_wqc[CC*CC];
__device__ __half g_wkc[CC*CC];
__device__ __half g_wvc[CC*CC];
__device__ __half g_wpc[CC*CC];
__device__ float  g_ksum[BB*CC];
__device__ float  g_kv[BB*HH*DD*DD];

__device__ __forceinline__ uint32_t smem_u32(const void* p) {
    uint32_t a;
    asm("{ .reg .u64 t; cvta.to.shared.u64 t, %1; cvt.u32.u64 %0, t; }" : "=r"(a) : "l"(p));
    return a;
}

#define CP_ASYNC16(saddr, gptr) \
    asm volatile("cp.async.cg.shared.global [%0], [%1], 16;" :: "r"(saddr), "l"(gptr))
#define CP_COMMIT() asm volatile("cp.async.commit_group;" ::: "memory")
#define CP_WAIT1()  asm volatile("cp.async.wait_group 1;" ::: "memory")

__device__ __forceinline__ void mma_f16(float* c, const uint32_t* a, const uint32_t* b) {
    asm volatile(
        "mma.sync.aligned.m16n8k16.row.col.f32.f16.f16.f32 "
        "{%0,%1,%2,%3}, {%4,%5,%6,%7}, {%8,%9}, {%0,%1,%2,%3};"
        : "+f"(c[0]), "+f"(c[1]), "+f"(c[2]), "+f"(c[3])
        : "r"(a[0]), "r"(a[1]), "r"(a[2]), "r"(a[3]), "r"(b[0]), "r"(b[1]));
}

#define LDSM_X4(r0, r1, r2, r3, addr) \
    asm volatile("ldmatrix.sync.aligned.m8n8.x4.shared.b16 {%0,%1,%2,%3}, [%4];" \
                 : "=r"(r0), "=r"(r1), "=r"(r2), "=r"(r3) : "r"(addr))
#define LDSM_X4_T(r0, r1, r2, r3, addr) \
    asm volatile("ldmatrix.sync.aligned.m8n8.x4.trans.shared.b16 {%0,%1,%2,%3}, [%4];" \
                 : "=r"(r0), "=r"(r1), "=r"(r2), "=r"(r3) : "r"(addr))

#define PITCHB 144
#define A_TILE_BYTES (128*PITCHB)      // 18432
#define STAGE_BYTES (2*A_TILE_BYTES)   // 36864   (Q/P kernel)
#define GEMM_SMEM (3*STAGE_BYTES)      // 110592
#define STAGE3_BYTES (3*A_TILE_BYTES)  // 55296   (KV kernel)
#define KV_SMEM (3*STAGE3_BYTES)       // 165888
#define NITER 16
#define KVPITCH 272                    // q/k/v epilogue tile pitch (136 halfs)

// Q epilogue smem layout (after mainloop)
#define Q_QOFF   0                     // q tile fp16 [128][272B]  -> 34816
#define Q_KVOFF  34816                 // kv fp16, 2 heads x [64][144B] -> +18432 = 53248
#define Q_KSOFF  53248                 // ksum fp32 [128] -> +512
#define Q_DSOFF  53760                 // dinv fp32 [128][2] -> +1024

// ============================================================================
// KV mega-kernel (512 threads) — unchanged (validated, 54.8% tensor)
// ============================================================================
__global__ __launch_bounds__(512, 1)
void gemm_kv(const __half* __restrict__ A,
             const __half* __restrict__ Wk, const __half* __restrict__ Wv,
             const float* __restrict__ bk, const float* __restrict__ bv,
             float* __restrict__ kv_out, float* __restrict__ ksum_out)
{
    extern __shared__ char smem[];
    const int tid  = threadIdx.x;
    const int wid  = tid >> 5;
    const int lane = tid & 31;
    const int g    = lane >> 2;
    const int tig  = lane & 3;
    const int grp  = wid >> 3;        // 0 = K, 1 = V
    const int kwid = wid & 7;
    const int wm   = kwid >> 1;
    const int wn   = kwid & 1;
    const int m0 = blockIdx.y * 128;
    const int n0 = blockIdx.x * 128;

    uint32_t sbase = smem_u32(smem);

    const int rA     = (lane & 7) + ((lane >> 3) & 1) * 8;
    const int kbyteA = ((lane >> 4) & 1) * 16;
    uint32_t aOff = (uint32_t)(wm * 32 + rA) * PITCHB + kbyteA;

    const int rB     = (lane & 7) + ((lane >> 4) & 1) * 8;
    const int kbyteB = ((lane >> 3) & 1) * 16;
    uint32_t bOff = (uint32_t)(1 + grp) * A_TILE_BYTES
                  + (uint32_t)(wn * 64 + rB) * PITCHB + kbyteB;

    float acc[2][8][4];
    #pragma unroll
    for (int mt = 0; mt < 2; mt++)
        #pragma unroll
        for (int nt = 0; nt < 8; nt++)
            #pragma unroll
            for (int r = 0; r < 4; r++) acc[mt][nt][r] = 0.f;

    auto issue3 = [&](int stage, int k0) {
        uint32_t sA = sbase + stage * STAGE3_BYTES;
        #pragma unroll
        for (int i = 0; i < 2; i++) {
            int f   = tid + i * 512;
            int row = f >> 3;
            int c   = f & 7;
            uint32_t soff = (uint32_t)row * PITCHB + c * 16;
            CP_ASYNC16(sA + soff, A + (size_t)(m0 + row) * CC + k0 + c * 8);
            CP_ASYNC16(sA + A_TILE_BYTES + soff,
                       Wk + (size_t)(n0 + row) * CC + k0 + c * 8);
            CP_ASYNC16(sA + 2 * A_TILE_BYTES + soff,
                       Wv + (size_t)(n0 + row) * CC + k0 + c * 8);
        }
        CP_COMMIT();
    };

    issue3(0, 0);
    issue3(1, 64);

    int stage = 0;
    #pragma unroll 1
    for (int it = 0; it < NITER; it++) {
        CP_WAIT1();
        __syncthreads();
        if (it + 2 < NITER) {
            int ns = stage + 2; if (ns >= 3) ns -= 3;
            issue3(ns, (it + 2) * 64);
        } else {
            CP_COMMIT();
        }

        uint32_t sstage = sbase + stage * STAGE3_BYTES;

        #pragma unroll
        for (int s = 0; s < 4; s++) {
            uint32_t sb = sstage + s * 32;
            uint32_t af[8];
            LDSM_X4(af[0], af[1], af[2], af[3], sb + aOff);
            LDSM_X4(af[4], af[5], af[6], af[7], sb + aOff + 16 * PITCHB);
            #pragma unroll
            for (int p = 0; p < 4; p++) {
                uint32_t bf[4];
                LDSM_X4(bf[0], bf[1], bf[2], bf[3],
                        sb + bOff + (uint32_t)p * (16 * PITCHB));
                mma_f16(acc[0][2*p    ], af,     bf);
                mma_f16(acc[0][2*p + 1], af,     bf + 2);
                mma_f16(acc[1][2*p    ], af + 4, bf);
                mma_f16(acc[1][2*p + 1], af + 4, bf + 2);
            }
        }
        stage++; if (stage >= 3) stage -= 3;
    }
    __syncthreads();

    const uint32_t svb = sbase;
    const uint32_t skb = sbase + 128 * KVPITCH;
    const float* bias = grp ? bv : bk;
    char* tilebase = smem + (grp ? 0 : 128 * KVPITCH);

    const int ncol0 = n0 + wn * 64;
    #pragma unroll
    for (int mt = 0; mt < 2; mt++) {
        #pragma unroll
        for (int half = 0; half < 2; half++) {
            int rloc = wm * 32 + mt * 16 + g + half * 8;
            float v[16];
            #pragma unroll
            for (int nt = 0; nt < 8; nt++) {
                int col = ncol0 + nt * 8 + tig * 2;
                v[nt * 2 + 0] = acc[mt][nt][half * 2 + 0] + __ldg(bias + col);
                v[nt * 2 + 1] = acc[mt][nt][half * 2 + 1] + __ldg(bias + col + 1);
            }
            if (grp == 0) {
                float mx = v[0];
                #pragma unroll
                for (int j = 1; j < 16; j++) mx = fmaxf(mx, v[j]);
                mx = fmaxf(mx, __shfl_xor_sync(0xffffffffu, mx, 1));
                mx = fmaxf(mx, __shfl_xor_sync(0xffffffffu, mx, 2));
                float s = 0.f;
                #pragma unroll
                for (int j = 0; j < 16; j++) { v[j] = __expf(v[j] - mx); s += v[j]; }
                s += __shfl_xor_sync(0xffffffffu, s, 1);
                s += __shfl_xor_sync(0xffffffffu, s, 2);
                float inv = 1.f / s;
                #pragma unroll
                for (int j = 0; j < 16; j++) v[j] *= inv;
            }
            char* dst = tilebase + (uint32_t)rloc * KVPITCH;
            #pragma unroll
            for (int nt = 0; nt < 8; nt++)
                *(__half2*)(dst + (wn * 64 + nt * 8 + tig * 2) * 2) =
                    __floats2half2_rn(v[nt * 2], v[nt * 2 + 1]);
        }
    }
    __syncthreads();

    if (grp == 0) {
        const int hh = wid >> 2;
        const int d0 = (wid & 3) * 16;
        const int bh = (m0 >> 12) * HH + (n0 >> 6) + hh;

        float accv[8][4];
        #pragma unroll
        for (int i = 0; i < 8; i++)
            #pragma unroll
            for (int r = 0; r < 4; r++) accv[i][r] = 0.f;

        uint32_t aAddr = skb + (uint32_t)((lane & 7) + ((lane >> 4) & 1) * 8) * KVPITCH
                       + (hh * 64 + d0 + ((lane >> 3) & 1) * 8) * 2;
        uint32_t bAddr = svb + (uint32_t)((lane & 7) + ((lane >> 3) & 1) * 8) * KVPITCH
                       + (hh * 64 + ((lane >> 4) & 1) * 8) * 2;

        #pragma unroll
        for (int k0 = 0; k0 < 128; k0 += 16) {
            uint32_t af[4];
            LDSM_X4_T(af[0], af[1], af[2], af[3], aAddr + (uint32_t)k0 * KVPITCH);
            #pragma unroll
            for (int et = 0; et < 4; et++) {
                uint32_t bf[4];
                LDSM_X4_T(bf[0], bf[1], bf[2], bf[3],
                          bAddr + (uint32_t)k0 * KVPITCH + et * 32);
                mma_f16(accv[et * 2    ], af, bf);
                mma_f16(accv[et * 2 + 1], af, bf + 2);
            }
        }

        #pragma unroll
        for (int et = 0; et < 4; et++)
            #pragma unroll
            for (int nn = 0; nn < 2; nn++)
                #pragma unroll
                for (int half = 0; half < 2; half++) {
                    int d = d0 + g + half * 8;
                    int e = et * 16 + nn * 8 + tig * 2;
                    float* base = kv_out + ((size_t)bh * 64 + d) * 64 + e;
                    atomicAdd(base    , accv[et * 2 + nn][half * 2 + 0]);
                    atomicAdd(base + 1, accv[et * 2 + nn][half * 2 + 1]);
                }
    } else {
        int t2 = tid - 256;
        int c  = t2 & 127;
        int r0 = (t2 >> 7) * 64;
        float s = 0.f;
        #pragma unroll 8
        for (int r = 0; r < 64; r++)
            s += __half2float(*(const __half*)(smem + 128 * KVPITCH +
                    (uint32_t)(r0 + r) * KVPITCH + c * 2));
        atomicAdd(&ksum_out[(m0 >> 12) * CC + n0 + c], s);
    }
}

// ============================================================================
// shared mainloop copy for Q/P
// ============================================================================
__device__ __forceinline__ void issue_copy(const __half* __restrict__ A,
                                           const __half* __restrict__ W,
                                           uint32_t sbase, int stage,
                                           int m0, int n0, int k0, int tid)
{
    uint32_t sA = sbase + stage * STAGE_BYTES;
    uint32_t sW = sA + A_TILE_BYTES;
    #pragma unroll
    for (int i = 0; i < 4; i++) {
        int f   = tid + i * 256;
        int row = f >> 3;
        int c   = f & 7;
        uint32_t soff = (uint32_t)row * PITCHB + c * 16;
        CP_ASYNC16(sA + soff, A + (size_t)(m0 + row) * CC + k0 + c * 8);
        CP_ASYNC16(sW + soff, W + (size_t)(n0 + row) * CC + k0 + c * 8);
    }
    CP_COMMIT();
}

// ============================================================================
// Q-GEMM: mainloop as R11; NEW tensor-core combine epilogue:
//   q (softmaxed, fp16) -> smem; dinv per (row, head) via smem pass;
//   out = q + (q @ kv) * dinv with kv fp16 in smem, 2x 32-col MMA passes.
// ============================================================================
__global__ __launch_bounds__(256, 2)
void gemm_q(const __half* __restrict__ A, const __half* __restrict__ W,
            const float* __restrict__ bias, __half* __restrict__ Cmat,
            const float* __restrict__ kvp, const float* __restrict__ ksump)
{
    extern __shared__ char smem[];
    const int tid  = threadIdx.x;
    const int wid  = tid >> 5;
    const int lane = tid & 31;
    const int g    = lane >> 2;
    const int tig  = lane & 3;
    const int wm   = wid >> 1;
    const int wn   = wid & 1;
    const int m0 = blockIdx.y * 128;
    const int n0 = blockIdx.x * 128;

    uint32_t sbase = smem_u32(smem);

    const int rA     = (lane & 7) + ((lane >> 3) & 1) * 8;
    const int kbyteA = ((lane >> 4) & 1) * 16;
    uint32_t aOff = (uint32_t)(wm * 32 + rA) * PITCHB + kbyteA;

    const int rB     = (lane & 7) + ((lane >> 4) & 1) * 8;
    const int kbyteB = ((lane >> 3) & 1) * 16;
    uint32_t bOff = A_TILE_BYTES + (uint32_t)(wn * 64 + rB) * PITCHB + kbyteB;

    float acc[2][8][4];
    #pragma unroll
    for (int mt = 0; mt < 2; mt++)
        #pragma unroll
        for (int nt = 0; nt < 8; nt++)
            #pragma unroll
            for (int r = 0; r < 4; r++) acc[mt][nt][r] = 0.f;

    issue_copy(A, W, sbase, 0, m0, n0, 0, tid);
    issue_copy(A, W, sbase, 1, m0, n0, 64, tid);

    int stage = 0;
    #pragma unroll 1
    for (int it = 0; it < NITER; it++) {
        CP_WAIT1();
        __syncthreads();
        if (it + 2 < NITER) {
            int ns = stage + 2; if (ns >= 3) ns -= 3;
            issue_copy(A, W, sbase, ns, m0, n0, (it + 2) * 64, tid);
        } else {
            CP_COMMIT();
        }

        uint32_t sstage = sbase + stage * STAGE_BYTES;

        #pragma unroll
        for (int s = 0; s < 4; s++) {
            uint32_t sb = sstage + s * 32;
            uint32_t af[8];
            LDSM_X4(af[0], af[1], af[2], af[3], sb + aOff);
            LDSM_X4(af[4], af[5], af[6], af[7], sb + aOff + 16 * PITCHB);
            #pragma unroll
            for (int p = 0; p < 4; p++) {
                uint32_t bf[4];
                LDSM_X4(bf[0], bf[1], bf[2], bf[3],
                        sb + bOff + (uint32_t)p * (16 * PITCHB));
                mma_f16(acc[0][2*p    ], af,     bf);
                mma_f16(acc[0][2*p + 1], af,     bf + 2);
                mma_f16(acc[1][2*p    ], af + 4, bf);
                mma_f16(acc[1][2*p + 1], af + 4, bf + 2);
            }
        }
        stage++; if (stage >= 3) stage -= 3;
    }
    __syncthreads();   // mainloop done; smem reused

    // ---- load kv (fp32 -> fp16, pitch 144) + ksum (fp32) into smem ----
    {
        int b  = m0 >> 12;
        int h0 = n0 >> 6;
        const float* kvg = kvp + ((size_t)(b * HH + h0) << 12);   // 8192 floats
        #pragma unroll
        for (int i = 0; i < 8; i++) {
            int L = (tid + i * 256) * 4;          // float index
            float4 vv = *(const float4*)(kvg + L);
            int h = L >> 12;
            int d = (L >> 6) & 63;
            int e = L & 63;
            __half2 p0 = __floats2half2_rn(vv.x, vv.y);
            __half2 p1 = __floats2half2_rn(vv.z, vv.w);
            char* dst = smem + Q_KVOFF + (h * 64 + d) * 144 + e * 2;
            *(__half2*)(dst    ) = p0;
            *(__half2*)(dst + 4) = p1;
        }
        if (tid < 32)
            *(float4*)(smem + Q_KSOFF + tid * 16) =
                *(const float4*)(ksump + b * CC + (h0 << 6) + tid * 4);
    }

    // ---- softmax per fragment-row; store q fp16 to smem tile ----
    const int ncol0 = n0 + wn * 64;
    #pragma unroll
    for (int mt = 0; mt < 2; mt++) {
        #pragma unroll
        for (int half = 0; half < 2; half++) {
            int rloc = wm * 32 + mt * 16 + g + half * 8;
            float v[16];
            #pragma unroll
            for (int nt = 0; nt < 8; nt++) {
                int col = ncol0 + nt * 8 + tig * 2;
                v[nt * 2 + 0] = acc[mt][nt][half * 2 + 0] + __ldg(bias + col);
                v[nt * 2 + 1] = acc[mt][nt][half * 2 + 1] + __ldg(bias + col + 1);
            }
            float mx = v[0];
            #pragma unroll
            for (int j = 1; j < 16; j++) mx = fmaxf(mx, v[j]);
            mx = fmaxf(mx, __shfl_xor_sync(0xffffffffu, mx, 1));
            mx = fmaxf(mx, __shfl_xor_sync(0xffffffffu, mx, 2));
            float s = 0.f;
            #pragma unroll
            for (int j = 0; j < 16; j++) { v[j] = __expf(v[j] - mx); s += v[j]; }
            s += __shfl_xor_sync(0xffffffffu, s, 1);
            s += __shfl_xor_sync(0xffffffffu, s, 2);
            float inv = 1.f / s;
            #pragma unroll
            for (int j = 0; j < 16; j++) v[j] *= inv;

            char* dst = smem + Q_QOFF + (uint32_t)rloc * KVPITCH;
            #pragma unroll
            for (int nt = 0; nt < 8; nt++)
                *(__half2*)(dst + (wn * 64 + nt * 8 + tig * 2) * 2) =
                    __floats2half2_rn(v[nt * 2], v[nt * 2 + 1]);
        }
    }
    __syncthreads();

    // ---- dinv[row][head] = 1 / (q_row_head . ksum_head); 2 threads/row ----
    {
        int row = tid >> 1;
        int h   = tid & 1;
        const __half2* qrow = (const __half2*)(smem + Q_QOFF + (uint32_t)row * KVPITCH + h * 128);
        const float*   kss  = (const float*)(smem + Q_KSOFF) + h * 64;
        float ds = 0.f;
        #pragma unroll
        for (int d2 = 0; d2 < 32; d2++) {
            float2 qf = __half22float2(qrow[d2]);
            ds += qf.x * kss[d2 * 2] + qf.y * kss[d2 * 2 + 1];
        }
        ((float*)(smem + Q_DSOFF))[row * 2 + h] = 1.f / ds;
    }
    __syncthreads();

    // ---- tensor combine: out = q + (q @ kv_head) * dinv ----
    // warp tile 32(rows) x 64(cols, = head wn); two 32-col passes.
    uint32_t aAddr2 = sbase + Q_QOFF + (uint32_t)(wm * 32 + rA) * KVPITCH
                    + wn * 128 + kbyteA;
    uint32_t bAddr2 = sbase + Q_KVOFF + (uint32_t)wn * 9216
                    + (uint32_t)((lane & 7) + ((lane >> 3) & 1) * 8) * 144
                    + ((lane >> 4) & 1) * 16;
    const float* dinv_s = (const float*)(smem + Q_DSOFF);

    #pragma unroll
    for (int pass = 0; pass < 2; pass++) {
        float acc3[2][4][4];
        #pragma unroll
        for (int a2 = 0; a2 < 2; a2++)
            #pragma unroll
            for (int b2 = 0; b2 < 4; b2++)
                #pragma unroll
                for (int r = 0; r < 4; r++) acc3[a2][b2][r] = 0.f;

        #pragma unroll
        for (int ks = 0; ks < 4; ks++) {
            uint32_t af2[8], bf2[8];
            LDSM_X4(af2[0], af2[1], af2[2], af2[3], aAddr2 + ks * 32);
            LDSM_X4(af2[4], af2[5], af2[6], af2[7], aAddr2 + 16 * KVPITCH + ks * 32);
            LDSM_X4_T(bf2[0], bf2[1], bf2[2], bf2[3],
                      bAddr2 + (uint32_t)ks * (16 * 144) + pass * 64);
            LDSM_X4_T(bf2[4], bf2[5], bf2[6], bf2[7],
                      bAddr2 + (uint32_t)ks * (16 * 144) + pass * 64 + 32);
            #pragma unroll
            for (int mt2 = 0; mt2 < 2; mt2++) {
                mma_f16(acc3[mt2][0], af2 + mt2 * 4, bf2);
                mma_f16(acc3[mt2][1], af2 + mt2 * 4, bf2 + 2);
                mma_f16(acc3[mt2][2], af2 + mt2 * 4, bf2 + 4);
                mma_f16(acc3[mt2][3], af2 + mt2 * 4, bf2 + 6);
            }
        }

        // store: out = q + acc3 * dinv
        #pragma unroll
        for (int mt2 = 0; mt2 < 2; mt2++) {
            #pragma unroll
            for (int half = 0; half < 2; half++) {
                int rloc = wm * 32 + mt2 * 16 + g + half * 8;
                float dinv = dinv_s[rloc * 2 + wn];
                #pragma unroll
                for (int nt = 0; nt < 4; nt++) {
                    int colq = wn * 64 + pass * 32 + nt * 8 + tig * 2;
                    __half2 qh = *(const __half2*)(smem + Q_QOFF +
                                    (uint32_t)rloc * KVPITCH + colq * 2);
                    float2 qf = __half22float2(qh);
                    float2 r;
                    r.x = qf.x + acc3[mt2][nt][half * 2 + 0] * dinv;
                    r.y = qf.y + acc3[mt2][nt][half * 2 + 1] * dinv;
                    *(__half2*)(Cmat + (size_t)(m0 + rloc) * CC + n0 + colq) =
                        __floats2half2_rn(r.x, r.y);
                }
            }
        }
    }
}

// ============================================================================
// P-GEMM (R11 shape, bias only, fp32 out)
// ============================================================================
__global__ __launch_bounds__(256, 2)
void gemm_p(const __half* __restrict__ A, const __half* __restrict__ W,
            const float* __restrict__ bias, float* __restrict__ Cmat)
{
    extern __shared__ char smem[];
    const int tid  = threadIdx.x;
    const int wid  = tid >> 5;
    const int lane = tid & 31;
    const int g    = lane >> 2;
    const int tig  = lane & 3;
    const int wm   = wid >> 1;
    const int wn   = wid & 1;
    const int m0 = blockIdx.y * 128;
    const int n0 = blockIdx.x * 128;

    uint32_t sbase = smem_u32(smem);

    const int rA     = (lane & 7) + ((lane >> 3) & 1) * 8;
    const int kbyteA = ((lane >> 4) & 1) * 16;
    uint32_t aOff = (uint32_t)(wm * 32 + rA) * PITCHB + kbyteA;

    const int rB     = (lane & 7) + ((lane >> 4) & 1) * 8;
    const int kbyteB = ((lane >> 3) & 1) * 16;
    uint32_t bOff = A_TILE_BYTES + (uint32_t)(wn * 64 + rB) * PITCHB + kbyteB;

    float acc[2][8][4];
    #pragma unroll
    for (int mt = 0; mt < 2; mt++)
        #pragma unroll
        for (int nt = 0; nt < 8; nt++)
            #pragma unroll
            for (int r = 0; r < 4; r++) acc[mt][nt][r] = 0.f;

    issue_copy(A, W, sbase, 0, m0, n0, 0, tid);
    issue_copy(A, W, sbase, 1, m0, n0, 64, tid);

    int stage = 0;
    #pragma unroll 1
    for (int it = 0; it < NITER; it++) {
        CP_WAIT1();
        __syncthreads();
        if (it + 2 < NITER) {
            int ns = stage + 2; if (ns >= 3) ns -= 3;
            issue_copy(A, W, sbase, ns, m0, n0, (it + 2) * 64, tid);
        } else {
            CP_COMMIT();
        }

        uint32_t sstage = sbase + stage * STAGE_BYTES;

        #pragma unroll
        for (int s = 0; s < 4; s++) {
            uint32_t sb = sstage + s * 32;
            uint32_t af[8];
            LDSM_X4(af[0], af[1], af[2], af[3], sb + aOff);
            LDSM_X4(af[4], af[5], af[6], af[7], sb + aOff + 16 * PITCHB);
            #pragma unroll
            for (int p = 0; p < 4; p++) {
                uint32_t bf[4];
                LDSM_X4(bf[0], bf[1], bf[2], bf[3],
                        sb + bOff + (uint32_t)p * (16 * PITCHB));
                mma_f16(acc[0][2*p    ], af,     bf);
                mma_f16(acc[0][2*p + 1], af,     bf + 2);
                mma_f16(acc[1][2*p    ], af + 4, bf);
                mma_f16(acc[1][2*p + 1], af + 4, bf + 2);
            }
        }
        stage++; if (stage >= 3) stage -= 3;
    }

    const int ncol0 = n0 + wn * 64;
    #pragma unroll
    for (int mt = 0; mt < 2; mt++) {
        #pragma unroll
        for (int half = 0; half < 2; half++) {
            int row = m0 + wm * 32 + mt * 16 + g + half * 8;
            float* op = Cmat + (size_t)row * CC + ncol0 + tig * 2;
            #pragma unroll
            for (int nt = 0; nt < 8; nt++) {
                int col = ncol0 + nt * 8 + tig * 2;
                float2 r;
                r.x = acc[mt][nt][half * 2 + 0] + __ldg(bias + col);
                r.y = acc[mt][nt][half * 2 + 1] + __ldg(bias + col + 1);
                *(float2*)(op + nt * 8) = r;
            }
        }
    }
}

// ============================================================================
// prep kernels — split in two so gemm_q is our 4th launch (profiled)
// ============================================================================
__device__ __forceinline__ void cvt8(const float* __restrict__ src,
                                     __half* __restrict__ dst, int i)
{
    float4 a = *(const float4*)(src + (size_t)i * 8);
    float4 b = *(const float4*)(src + (size_t)i * 8 + 4);
    __half2 h0 = __floats2half2_rn(a.x, a.y);
    __half2 h1 = __floats2half2_rn(a.z, a.w);
    __half2 h2 = __floats2half2_rn(b.x, b.y);
    __half2 h3 = __floats2half2_rn(b.z, b.w);
    uint4 r;
    r.x = *(uint32_t*)&h0; r.y = *(uint32_t*)&h1;
    r.z = *(uint32_t*)&h2; r.w = *(uint32_t*)&h3;
    *(uint4*)(dst + (size_t)i * 8) = r;
}

// prep_a: cvt y (blocks [0,8192)) + 4 weights (blocks [8192,10240))
__global__ void prep_a_kernel(const float* y, const float* w0, const float* w1,
                              const float* w2, const float* w3,
                              __half* yc, __half* d0, __half* d1,
                              __half* d2, __half* d3)
{
    int b = blockIdx.x;
    int t = threadIdx.x;
    if (b < 8192) {
        cvt8(y, yc, b * 256 + t);
    } else {
        int w = (b - 8192) >> 9;
        int i = ((b - 8192) & 511) * 256 + t;
        const float* s; __half* d;
        switch (w) {
            case 0:  s = w0; d = d0; break;
            case 1:  s = w1; d = d1; break;
            case 2:  s = w2; d = d2; break;
            default: s = w3; d = d3; break;
        }
        cvt8(s, d, i);
    }
}

// prep_b: cvt x (blocks [0,8192)) + zero kv/ksum (blocks [8192,8448))
__global__ void prep_b_kernel(const float* x, __half* xc,
                              float* kvz, float* ksz)
{
    int b = blockIdx.x;
    int t = threadIdx.x;
    if (b < 8192) {
        cvt8(x, xc, b * 256 + t);
    } else {
        int i = (b - 8192) * 256 + t;      // 0..65535
        *(float4*)(kvz + (size_t)i * 4) = make_float4(0.f, 0.f, 0.f, 0.f);
        if (i < 1024)
            *(float4*)(ksz + (size_t)i * 4) = make_float4(0.f, 0.f, 0.f, 0.f);
    }
}

// ============================================================================
// Launch: prep_a(1), prep_b(2), kv(3), q(4 = profiled), p(5)
// ============================================================================
extern "C" void kernel_launch(void* const* d_in, const int* in_sizes, int n_in,
                              void* d_out, int out_size)
{
    const float* x  = (const float*)d_in[0];
    const float* y  = (const float*)d_in[1];
    const float* Wq = (const float*)d_in[2];
    const float* bq = (const float*)d_in[3];
    const float* Wk = (const float*)d_in[4];
    const float* bk = (const float*)d_in[5];
    const float* Wv = (const float*)d_in[6];
    const float* bv = (const float*)d_in[7];
    const float* Wp = (const float*)d_in[8];
    const float* bp = (const float*)d_in[9];
    float* out = (float*)d_out;

    __half *attn, *xc, *yc, *wqc, *wkc, *wvc, *wpc;
    float *ksum, *kv;
    cudaGetSymbolAddress((void**)&attn, g_attn);
    cudaGetSymbolAddress((void**)&xc,   g_xc);
    cudaGetSymbolAddress((void**)&yc,   g_yc);
    cudaGetSymbolAddress((void**)&wqc,  g_wqc);
    cudaGetSymbolAddress((void**)&wkc,  g_wkc);
    cudaGetSymbolAddress((void**)&wvc,  g_wvc);
    cudaGetSymbolAddress((void**)&wpc,  g_wpc);
    cudaGetSymbolAddress((void**)&ksum, g_ksum);
    cudaGetSymbolAddress((void**)&kv,   g_kv);

    cudaFuncSetAttribute(gemm_kv, cudaFuncAttributeMaxDynamicSharedMemorySize, KV_SMEM);
    cudaFuncSetAttribute(gemm_q,  cudaFuncAttributeMaxDynamicSharedMemorySize, GEMM_SMEM);
    cudaFuncSetAttribute(gemm_p,  cudaFuncAttributeMaxDynamicSharedMemorySize, GEMM_SMEM);

    dim3 ggrid(CC / 128, MM / 128);  // (8, 128)

    // 1: prep_a (cvt y + all weights)
    prep_a_kernel<<<10240, 256>>>(y, Wk, Wv, Wq, Wp, yc, wkc, wvc, wqc, wpc);
    // 2: prep_b (cvt x + zero kv/ksum)
    prep_b_kernel<<<8448, 256>>>(x, xc, kv, ksum);
    // 3: merged K+V GEMM -> kv, ksum
    gemm_kv<<<ggrid, 512, KV_SMEM>>>(yc, wkc, wvc, bk, bv, kv, ksum);
    // 4: Q-GEMM with tensor-core combine epilogue -> attn (fp16) [PROFILED]
    gemm_q<<<ggrid, 256, GEMM_SMEM>>>(xc, wqc, bq, attn, kv, ksum);
    // 5: output projection -> fp32 out
    gemm_p<<<ggrid, 256, GEMM_SMEM>>>(attn, wpc, bp, out);
}